// round 5
// baseline (speedup 1.0000x reference)
#include <cuda_runtime.h>
#include <cstdint>

#define BSZ 2
#define LQ 2048
#define DM 256
#define MROWS (BSZ*LQ)

// scratch
__device__ float g_Q[MROWS*DM];
__device__ float g_K[MROWS*DM];
__device__ float g_V[MROWS*DM];
__device__ float g_O[MROWS*DM];
__device__ float g_msg[MROWS*DM];
__device__ float g_hid[MROWS*2*DM];

// ---------------------------------------------------------------------------
__device__ __forceinline__ unsigned f2tf(float x){
    unsigned u; asm("cvt.rna.tf32.f32 %0,%1;" : "=r"(u) : "f"(x)); return u;
}
__device__ __forceinline__ void mma8(float* c, const unsigned* a, const unsigned* b){
    asm volatile("mma.sync.aligned.m16n8k8.row.col.f32.tf32.tf32.f32 "
        "{%0,%1,%2,%3},{%4,%5,%6,%7},{%8,%9},{%0,%1,%2,%3};"
        : "+f"(c[0]), "+f"(c[1]), "+f"(c[2]), "+f"(c[3])
        : "r"(a[0]), "r"(a[1]), "r"(a[2]), "r"(a[3]), "r"(b[0]), "r"(b[1]));
}
// e^x for x <= 0, FMA-pipe only. rel err ~2e-6.
__device__ __forceinline__ float fast_exp(float x){
    float y = x * 1.44269504f;
    y = fmaxf(y, -126.0f);
    float z = y + 12582912.0f;
    int   n = __float_as_int(z) - 0x4B400000;
    float f = y - (z - 12582912.0f);
    float p = 1.33336e-3f;
    p = fmaf(p, f, 9.61813e-3f);
    p = fmaf(p, f, 5.55041e-2f);
    p = fmaf(p, f, 2.40227e-1f);
    p = fmaf(p, f, 6.93147e-1f);
    p = fmaf(p, f, 1.0f);
    return p * __int_as_float((n + 127) << 23);
}

// ---------------------------------------------------------------------------
// tf32 GEMM: BM=32, BN=256, BK=32, 256 threads, double-buffered smem. (R4 proven)
// ---------------------------------------------------------------------------
#define AM_PLAIN 0
#define AM_ADD   1
#define AM_CAT   2
#define EPI_NONE 0
#define EPI_RELU 1
#define EPI_LN   2
#define EPI_LNR  3

#define AS_STR 36
#define BS_STR 264
#define BUF_WORDS (32*AS_STR + 32*BS_STR)
#define SM_GEMM (2*BUF_WORDS*4)

template<int KD, int AM>
__device__ __forceinline__ void gload(const float* __restrict__ A1, const float* __restrict__ A2,
    const float* __restrict__ B, int ldb, int n0, int row0, int kc, int tid,
    float4& pa, float4* pb)
{
    int ar = tid >> 3, ac4 = (tid & 7) << 2;
    int col = kc*32 + ac4;
    if (AM == AM_ADD){
        float4 x1 = *(const float4*)(A1 + (row0+ar)*KD + col);
        float4 x2 = *(const float4*)(A2 + (row0+ar)*KD + col);
        pa = make_float4(x1.x+x2.x, x1.y+x2.y, x1.z+x2.z, x1.w+x2.w);
    } else if (AM == AM_CAT){
        const float* s = (col < 256) ? (A1 + (row0+ar)*256 + col)
                                     : (A2 + (row0+ar)*256 + (col-256));
        pa = *(const float4*)s;
    } else {
        pa = *(const float4*)(A1 + (row0+ar)*KD + col);
    }
    #pragma unroll
    for (int i = 0; i < 8; i++){
        int id = tid + i*256;
        int r = id >> 6, c4 = (id & 63) << 2;
        pb[i] = *(const float4*)(B + (kc*32 + r)*ldb + n0 + c4);
    }
}

__device__ __forceinline__ void sstore(unsigned* Abuf, unsigned* Bbuf, int tid,
    const float4& pa, const float4* pb)
{
    int ar = tid >> 3, ac4 = (tid & 7) << 2;
    unsigned* d = &Abuf[ar*AS_STR + ac4];
    d[0]=f2tf(pa.x); d[1]=f2tf(pa.y); d[2]=f2tf(pa.z); d[3]=f2tf(pa.w);
    #pragma unroll
    for (int i = 0; i < 8; i++){
        int id = tid + i*256;
        int r = id >> 6, c4 = (id & 63) << 2;
        unsigned* e = &Bbuf[r*BS_STR + c4];
        e[0]=f2tf(pb[i].x); e[1]=f2tf(pb[i].y); e[2]=f2tf(pb[i].z); e[3]=f2tf(pb[i].w);
    }
}

template<int KD, int AM, int EPI>
__device__ __forceinline__ void gemm_body(
    const float* __restrict__ A1, const float* __restrict__ A2,
    const float* __restrict__ B, int ldb, int n0,
    const float* __restrict__ gamma, const float* __restrict__ beta,
    const float* __restrict__ resid, float* __restrict__ C, int ldc)
{
    extern __shared__ unsigned smu[];
    const int KC = KD/32;
    int tid = threadIdx.x;
    int w = tid >> 5, lane = tid & 31;
    int wm = w >> 2, wn = w & 3;
    int g4 = lane >> 2, tig = lane & 3;
    int row0 = blockIdx.x * 32;

    float acc[8][4];
    #pragma unroll
    for (int nt = 0; nt < 8; nt++)
        #pragma unroll
        for (int i = 0; i < 4; i++) acc[nt][i] = 0.f;

    float4 pa, pb[8];
    gload<KD, AM>(A1, A2, B, ldb, n0, row0, 0, tid, pa, pb);
    sstore(smu, smu + 32*AS_STR, tid, pa, pb);
    __syncthreads();

    for (int kc = 0; kc < KC; kc++){
        unsigned* Abuf = smu + (kc & 1)*BUF_WORDS;
        unsigned* Bbuf = Abuf + 32*AS_STR;
        if (kc + 1 < KC)
            gload<KD, AM>(A1, A2, B, ldb, n0, row0, kc+1, tid, pa, pb);
        #pragma unroll
        for (int kk = 0; kk < 4; kk++){
            int k0 = kk*8;
            unsigned a[4], bf[2];
            int r = wm*16 + g4;
            a[0] = Abuf[r*AS_STR + k0 + tig];
            a[1] = Abuf[(r+8)*AS_STR + k0 + tig];
            a[2] = Abuf[r*AS_STR + k0 + tig + 4];
            a[3] = Abuf[(r+8)*AS_STR + k0 + tig + 4];
            #pragma unroll
            for (int nt = 0; nt < 8; nt++){
                int n = wn*64 + nt*8 + g4;
                bf[0] = Bbuf[(k0 + tig)*BS_STR + n];
                bf[1] = Bbuf[(k0 + tig + 4)*BS_STR + n];
                mma8(acc[nt], a, bf);
            }
        }
        if (kc + 1 < KC){
            unsigned* An = smu + ((kc+1) & 1)*BUF_WORDS;
            sstore(An, An + 32*AS_STR, tid, pa, pb);
        }
        __syncthreads();
    }

    if (EPI == EPI_NONE || EPI == EPI_RELU){
        int rl = row0 + wm*16 + g4;
        #pragma unroll
        for (int nt = 0; nt < 8; nt++){
            int col = n0 + wn*64 + nt*8 + 2*tig;
            float v0 = acc[nt][0], v1 = acc[nt][1];
            float v2 = acc[nt][2], v3 = acc[nt][3];
            if (EPI == EPI_RELU){
                v0=fmaxf(v0,0.f); v1=fmaxf(v1,0.f); v2=fmaxf(v2,0.f); v3=fmaxf(v3,0.f);
            }
            *(float2*)(C + rl*ldc + col)     = make_float2(v0, v1);
            *(float2*)(C + (rl+8)*ldc + col) = make_float2(v2, v3);
        }
    } else {
        float2* red = (float2*)smu;
        float s1[2] = {0,0}, s2[2] = {0,0};
        #pragma unroll
        for (int nt = 0; nt < 8; nt++){
            float c0=acc[nt][0], c1=acc[nt][1], c2=acc[nt][2], c3=acc[nt][3];
            s1[0] += c0+c1; s2[0] += c0*c0 + c1*c1;
            s1[1] += c2+c3; s2[1] += c2*c2 + c3*c3;
        }
        #pragma unroll
        for (int hb = 0; hb < 2; hb++){
            float v1 = s1[hb], v2 = s2[hb];
            v1 += __shfl_xor_sync(~0u, v1, 1); v1 += __shfl_xor_sync(~0u, v1, 2);
            v2 += __shfl_xor_sync(~0u, v2, 1); v2 += __shfl_xor_sync(~0u, v2, 2);
            if (tig == 0){
                int r = wm*16 + g4 + hb*8;
                red[r*4 + wn] = make_float2(v1, v2);
            }
        }
        __syncthreads();
        #pragma unroll
        for (int hb = 0; hb < 2; hb++){
            int r = wm*16 + g4 + hb*8;
            float S1 = 0.f, S2 = 0.f;
            #pragma unroll
            for (int j = 0; j < 4; j++){ float2 e = red[r*4+j]; S1 += e.x; S2 += e.y; }
            float mean = S1 * (1.f/256.f);
            float var  = S2 * (1.f/256.f) - mean*mean;
            float inv  = rsqrtf(var + 1e-5f);
            int grow = row0 + r;
            #pragma unroll
            for (int nt = 0; nt < 8; nt++){
                int col = wn*64 + nt*8 + 2*tig;
                float c0 = acc[nt][hb*2], c1 = acc[nt][hb*2+1];
                float o0 = (c0 - mean)*inv*gamma[col]   + beta[col];
                float o1 = (c1 - mean)*inv*gamma[col+1] + beta[col+1];
                if (EPI == EPI_LNR){
                    o0 += resid[grow*256 + col];
                    o1 += resid[grow*256 + col + 1];
                }
                *(float2*)(C + grow*ldc + col) = make_float2(o0, o1);
            }
        }
    }
}

__global__ void __launch_bounds__(256) k_qkv(
    const float* x, const float* xpe, const float* src, const float* spe,
    const float* Wq, const float* Wk, const float* Wv)
{
    if (blockIdx.z == 0)      gemm_body<256, AM_ADD,   EPI_NONE>(x,   xpe, Wq, 256, 0, 0,0,0, g_Q, 256);
    else if (blockIdx.z == 1) gemm_body<256, AM_ADD,   EPI_NONE>(src, spe, Wk, 256, 0, 0,0,0, g_K, 256);
    else                      gemm_body<256, AM_PLAIN, EPI_NONE>(src, 0,   Wv, 256, 0, 0,0,0, g_V, 256);
}
__global__ void __launch_bounds__(256) k_merge(const float* Wmg, const float* gg, const float* bb){
    gemm_body<256, AM_PLAIN, EPI_LN>(g_O, 0, Wmg, 256, 0, gg, bb, 0, g_msg, 256);
}
__global__ void __launch_bounds__(256) k_mlp1(const float* x, const float* Wm1){
    gemm_body<512, AM_CAT, EPI_RELU>(x, g_msg, Wm1, 512, blockIdx.y*256, 0,0,0, g_hid, 512);
}
__global__ void __launch_bounds__(256) k_mlp2(const float* Wm2, const float* gg, const float* bb,
                                              const float* x, float* out){
    gemm_body<512, AM_PLAIN, EPI_LNR>(g_hid, 0, Wm2, 256, 0, gg, bb, x, out, 256);
}

// ---------------------------------------------------------------------------
// Flash attention v2. CTA = (b, 32 l-rows, 1 head). 8 warps:
//   ws = w&3  : 4-way split-KV group (s-tiles ws, ws+4, ...), own online stats
//   wm = w>>2 : l-half (16 rows)
// comp/source_mask load straight to registers (no smem). K prefetched at loop
// top, V right after softmax; P tile overlays the K smem region.
// ---------------------------------------------------------------------------
#define QS_STR 68
#define KS_STR 68
#define VS_STR 72
#define PS_STR 36
#define OS_STR 66

#define AOF_K   2176                   // after Qs (32*68)
#define AOF_V   (AOF_K + 4*2176)       // 10880
#define AOF_STM (AOF_V + 4*2304)      // 20096
#define AOF_STS (AOF_STM + 128)       // 20224
#define AOF_XM  (AOF_STS + 128)       // 20352
#define ATTN_WORDS (AOF_XM + 32)      // 20384
#define SM_ATTN (ATTN_WORDS*4)        // 81536 bytes -> 2 CTAs/SM

__global__ void __launch_bounds__(256, 2) k_attn(
    const float* __restrict__ Qm, const float* __restrict__ Km, const float* __restrict__ Vm,
    const float* __restrict__ comp, const int* __restrict__ xmask, const int* __restrict__ smask,
    float* __restrict__ O)
{
    extern __shared__ float sm[];
    int tid = threadIdx.x;
    int w = tid >> 5, lane = tid & 31;
    int ws = w & 3, wm = w >> 2;
    int g4 = lane >> 2, tig = lane & 3;
    int b = blockIdx.z, hq = blockIdx.y, l0 = blockIdx.x * 32;
    int dbase = hq * 64;

    unsigned* Qs = (unsigned*)sm;
    unsigned* Kg = (unsigned*)sm + AOF_K + ws*2176;
    unsigned* Vg = (unsigned*)sm + AOF_V + ws*2304;
    unsigned* Pw = Kg + wm*576;                      // P overlays K region
    float* statm = sm + AOF_STM;
    float* stats = sm + AOF_STS;
    int*   xm    = (int*)(sm + AOF_XM);

    // ---- stage Q (this head's 64 cols, tf32) ----
    #pragma unroll
    for (int i = 0; i < 2; i++){
        int f4i = tid + i*256;
        int r = f4i >> 4, c4 = (f4i & 15) << 2;
        float4 v = *(const float4*)(Qm + (b*LQ + l0 + r)*256 + dbase + c4);
        unsigned* d = &Qs[r*QS_STR + c4];
        d[0]=f2tf(v.x); d[1]=f2tf(v.y); d[2]=f2tf(v.z); d[3]=f2tf(v.w);
    }
    if (tid < 32) xm[tid] = xmask[b*LQ + l0 + tid];

    // ---- group-cooperative K/V tile load geometry (64 threads per ws group) ----
    int id2 = wm*32 + lane;
    int krow = id2 >> 1, c0 = (id2 & 1) * 32;

    // preload tile 0 of this group
    {
        int s0 = ws*32;
        #pragma unroll
        for (int i = 0; i < 8; i++){
            const float* gp = Km + (b*LQ + s0 + krow)*256 + dbase + c0 + i*4;
            float4 vk = *(const float4*)gp;
            unsigned* dk = &Kg[krow*KS_STR + c0 + i*4];
            dk[0]=f2tf(vk.x); dk[1]=f2tf(vk.y); dk[2]=f2tf(vk.z); dk[3]=f2tf(vk.w);
            const float* gv = Vm + (b*LQ + s0 + krow)*256 + dbase + c0 + i*4;
            float4 vv = *(const float4*)gv;
            unsigned* dv = &Vg[krow*VS_STR + c0 + i*4];
            dv[0]=f2tf(vv.x); dv[1]=f2tf(vv.y); dv[2]=f2tf(vv.z); dv[3]=f2tf(vv.w);
        }
    }
    __syncthreads();

    float o[8][4];
    #pragma unroll
    for (int nt = 0; nt < 8; nt++)
        #pragma unroll
        for (int i = 0; i < 4; i++) o[nt][i] = 0.f;
    float rmax[2] = {-1e30f, -1e30f};
    float rsum[2] = {0.f, 0.f};

    int grl = b*LQ + l0 + wm*16 + g4;        // global q row (low)
    int barid = 1 + ws;

    for (int t = 0; t < 16; t++){
        int s0  = (t*4 + ws)*32;
        int s0n = ((t+1)*4 + ws)*32;

        // prefetch next K tile into regs
        float4 pk[8];
        if (t < 15){
            #pragma unroll
            for (int i = 0; i < 8; i++)
                pk[i] = *(const float4*)(Km + (b*LQ + s0n + krow)*256 + dbase + c0 + i*4);
        }
        // comp + smask straight to regs (latency hidden by QK mma)
        float2 crl[4], crh[4]; int2 ms2[4];
        #pragma unroll
        for (int nt = 0; nt < 4; nt++){
            int se = s0 + nt*8 + 2*tig;
            crl[nt] = *(const float2*)(comp + (long)grl*LQ + se);
            crh[nt] = *(const float2*)(comp + (long)(grl+8)*LQ + se);
            ms2[nt] = *(const int2*)(smask + b*LQ + se);
        }

        // ---- QK^T ----
        float S[4][4];
        #pragma unroll
        for (int nt = 0; nt < 4; nt++)
            #pragma unroll
            for (int i = 0; i < 4; i++) S[nt][i] = 0.f;
        #pragma unroll
        for (int kk = 0; kk < 8; kk++){
            int k0 = kk*8;
            unsigned a[4], bf[2];
            int r = wm*16 + g4;
            a[0] = Qs[r*QS_STR + k0 + tig];
            a[1] = Qs[(r+8)*QS_STR + k0 + tig];
            a[2] = Qs[r*QS_STR + k0 + tig + 4];
            a[3] = Qs[(r+8)*QS_STR + k0 + tig + 4];
            #pragma unroll
            for (int nt = 0; nt < 4; nt++){
                int s = nt*8 + g4;
                bf[0] = Kg[s*KS_STR + k0 + tig];
                bf[1] = Kg[s*KS_STR + k0 + tig + 4];
                mma8(S[nt], a, bf);
            }
        }
        asm volatile("bar.sync %0, 64;" :: "r"(barid) : "memory");  // K reads done

        // ---- softmax (warp-local rows) ----
        int xml = xm[wm*16 + g4], xmh = xm[wm*16 + g4 + 8];
        float tmaxl = -1e30f, tmaxh = -1e30f;
        #pragma unroll
        for (int nt = 0; nt < 4; nt++){
            float v0 = (xml && !ms2[nt].x) ? -1e30f : S[nt][0]*crl[nt].x*0.125f;
            float v1 = (xml && !ms2[nt].y) ? -1e30f : S[nt][1]*crl[nt].y*0.125f;
            float v2 = (xmh && !ms2[nt].x) ? -1e30f : S[nt][2]*crh[nt].x*0.125f;
            float v3 = (xmh && !ms2[nt].y) ? -1e30f : S[nt][3]*crh[nt].y*0.125f;
            S[nt][0]=v0; S[nt][1]=v1; S[nt][2]=v2; S[nt][3]=v3;
            tmaxl = fmaxf(tmaxl, fmaxf(v0, v1));
            tmaxh = fmaxf(tmaxh, fmaxf(v2, v3));
        }
        tmaxl = fmaxf(tmaxl, __shfl_xor_sync(~0u, tmaxl, 1));
        tmaxl = fmaxf(tmaxl, __shfl_xor_sync(~0u, tmaxl, 2));
        tmaxh = fmaxf(tmaxh, __shfl_xor_sync(~0u, tmaxh, 1));
        tmaxh = fmaxf(tmaxh, __shfl_xor_sync(~0u, tmaxh, 2));
        float ml = fmaxf(rmax[0], tmaxl), mh = fmaxf(rmax[1], tmaxh);
        float al = fast_exp(rmax[0] - ml), ah = fast_exp(rmax[1] - mh);
        rmax[0] = ml; rmax[1] = mh;
        float tsl = 0.f, tsh = 0.f;
        #pragma unroll
        for (int nt = 0; nt < 4; nt++){
            float p0 = fast_exp(S[nt][0] - ml);
            float p1 = fast_exp(S[nt][1] - ml);
            float p2 = fast_exp(S[nt][2] - mh);
            float p3 = fast_exp(S[nt][3] - mh);
            tsl += p0 + p1; tsh += p2 + p3;
            int se = nt*8 + 2*tig;
            *(uint2*)&Pw[g4*PS_STR + se]     = make_uint2(f2tf(p0), f2tf(p1));
            *(uint2*)&Pw[(g4+8)*PS_STR + se] = make_uint2(f2tf(p2), f2tf(p3));
        }
        tsl += __shfl_xor_sync(~0u, tsl, 1); tsl += __shfl_xor_sync(~0u, tsl, 2);
        tsh += __shfl_xor_sync(~0u, tsh, 1); tsh += __shfl_xor_sync(~0u, tsh, 2);
        rsum[0] = rsum[0]*al + tsl;
        rsum[1] = rsum[1]*ah + tsh;
        #pragma unroll
        for (int nt = 0; nt < 8; nt++){
            o[nt][0] *= al; o[nt][1] *= al;
            o[nt][2] *= ah; o[nt][3] *= ah;
        }
        __syncwarp();

        // prefetch next V tile into regs (latency hidden by PV mma)
        float4 pv[8];
        if (t < 15){
            #pragma unroll
            for (int i = 0; i < 8; i++)
                pv[i] = *(const float4*)(Vm + (b*LQ + s0n + krow)*256 + dbase + c0 + i*4);
        }

        // ---- P @ V ----
        #pragma unroll
        for (int kk = 0; kk < 4; kk++){
            int k0 = kk*8;
            unsigned a[4], bf[2];
            a[0] = Pw[g4*PS_STR + k0 + tig];
            a[1] = Pw[(g4+8)*PS_STR + k0 + tig];
            a[2] = Pw[g4*PS_STR + k0 + tig + 4];
            a[3] = Pw[(g4+8)*PS_STR + k0 + tig + 4];
            #pragma unroll
            for (int nt = 0; nt < 8; nt++){
                int d = nt*8 + g4;
                bf[0] = Vg[(k0 + tig)*VS_STR + d];
                bf[1] = Vg[(k0 + tig + 4)*VS_STR + d];
                mma8(o[nt], a, bf);
            }
        }
        asm volatile("bar.sync %0, 64;" :: "r"(barid) : "memory");  // P/V reads done

        // store prefetched K/V for next tile
        if (t < 15){
            #pragma unroll
            for (int i = 0; i < 8; i++){
                unsigned* dk = &Kg[krow*KS_STR + c0 + i*4];
                dk[0]=f2tf(pk[i].x); dk[1]=f2tf(pk[i].y); dk[2]=f2tf(pk[i].z); dk[3]=f2tf(pk[i].w);
                unsigned* dv = &Vg[krow*VS_STR + c0 + i*4];
                dv[0]=f2tf(pv[i].x); dv[1]=f2tf(pv[i].y); dv[2]=f2tf(pv[i].z); dv[3]=f2tf(pv[i].w);
            }
            asm volatile("bar.sync %0, 64;" :: "r"(barid) : "memory");  // stores visible
        }
    }

    // ---- merge the 4 split-KV groups ----
    if (tig == 0){
        int r = wm*16 + g4;
        statm[ws*32 + r]     = rmax[0];
        stats[ws*32 + r]     = rsum[0];
        statm[ws*32 + r + 8] = rmax[1];
        stats[ws*32 + r + 8] = rsum[1];
    }
    __syncthreads();

    float sc[2];
    #pragma unroll
    for (int hb = 0; hb < 2; hb++){
        int r = wm*16 + g4 + hb*8;
        float m0 = statm[r], m1 = statm[32 + r], m2 = statm[64 + r], m3 = statm[96 + r];
        float m = fmaxf(fmaxf(m0, m1), fmaxf(m2, m3));
        float den = stats[r]      * fast_exp(m0 - m)
                  + stats[32 + r] * fast_exp(m1 - m)
                  + stats[64 + r] * fast_exp(m2 - m)
                  + stats[96 + r] * fast_exp(m3 - m);
        sc[hb] = fast_exp(rmax[hb] - m) / den;
    }

    float* Osm = sm + AOF_K;   // 4 groups x 32 x OS_STR, overlays K/P region
    #pragma unroll
    for (int nt = 0; nt < 8; nt++){
        int r = wm*16 + g4;
        int dd = nt*8 + 2*tig;
        *(float2*)&Osm[ws*2112 + r*OS_STR + dd] =
            make_float2(o[nt][0]*sc[0], o[nt][1]*sc[0]);
        *(float2*)&Osm[ws*2112 + (r+8)*OS_STR + dd] =
            make_float2(o[nt][2]*sc[1], o[nt][3]*sc[1]);
    }
    __syncthreads();

    // final cross-group sum + store
    {
        int r = tid >> 3, d0 = (tid & 7) * 8;
        float* op = O + (long)(b*LQ + l0 + r)*256 + dbase + d0;
        #pragma unroll
        for (int j = 0; j < 8; j++){
            float v = Osm[0*2112 + r*OS_STR + d0 + j]
                    + Osm[1*2112 + r*OS_STR + d0 + j]
                    + Osm[2*2112 + r*OS_STR + d0 + j]
                    + Osm[3*2112 + r*OS_STR + d0 + j];
            op[j] = v;
        }
    }
}

// ---------------------------------------------------------------------------
extern "C" void kernel_launch(void* const* d_in, const int* in_sizes, int n_in,
                              void* d_out, int out_size)
{
    const float* x    = (const float*)d_in[0];
    const float* src  = (const float*)d_in[1];
    const float* xpe  = (const float*)d_in[2];
    const float* spe  = (const float*)d_in[3];
    const int* xmask  = (const int*)d_in[4];
    const int* smask  = (const int*)d_in[5];
    const float* comp = (const float*)d_in[6];
    const float* Wq   = (const float*)d_in[7];
    const float* Wk   = (const float*)d_in[8];
    const float* Wv   = (const float*)d_in[9];
    const float* Wmg  = (const float*)d_in[10];
    const float* Wm1  = (const float*)d_in[11];
    const float* Wm2  = (const float*)d_in[12];
    const float* ln1g = (const float*)d_in[13];
    const float* ln1b = (const float*)d_in[14];
    const float* ln2g = (const float*)d_in[15];
    const float* ln2b = (const float*)d_in[16];
    float* out = (float*)d_out;

    float *Qp, *Kp, *Vp, *Op;
    cudaGetSymbolAddress((void**)&Qp, g_Q);
    cudaGetSymbolAddress((void**)&Kp, g_K);
    cudaGetSymbolAddress((void**)&Vp, g_V);
    cudaGetSymbolAddress((void**)&Op, g_O);

    cudaFuncSetAttribute(k_qkv,   cudaFuncAttributeMaxDynamicSharedMemorySize, SM_GEMM);
    cudaFuncSetAttribute(k_merge, cudaFuncAttributeMaxDynamicSharedMemorySize, SM_GEMM);
    cudaFuncSetAttribute(k_mlp1,  cudaFuncAttributeMaxDynamicSharedMemorySize, SM_GEMM);
    cudaFuncSetAttribute(k_mlp2,  cudaFuncAttributeMaxDynamicSharedMemorySize, SM_GEMM);
    cudaFuncSetAttribute(k_attn,  cudaFuncAttributeMaxDynamicSharedMemorySize, SM_ATTN);

    k_qkv <<<dim3(MROWS/32, 1, 3), 256, SM_GEMM>>>(x, xpe, src, spe, Wq, Wk, Wv);
    k_attn<<<dim3(LQ/32, 4, BSZ), 256, SM_ATTN>>>(Qp, Kp, Vp, comp, xmask, smask, Op);
    k_merge<<<MROWS/32,            256, SM_GEMM>>>(Wmg, ln1g, ln1b);
    k_mlp1<<<dim3(MROWS/32, 2),    256, SM_GEMM>>>(x, Wm1);
    k_mlp2<<<MROWS/32,             256, SM_GEMM>>>(Wm2, ln2g, ln2b, x, out);
}

// round 6
// speedup vs baseline: 1.7708x; 1.7708x over previous
#include <cuda_runtime.h>
#include <cstdint>

#define BSZ 2
#define LQ 2048
#define DM 256
#define MROWS (BSZ*LQ)
#define SPLITS 2

// scratch
__device__ float g_Q[MROWS*DM];
__device__ float g_K[MROWS*DM];
__device__ float g_V[MROWS*DM];
__device__ float g_O[MROWS*DM];
__device__ float g_msg[MROWS*DM];
__device__ float g_hid[MROWS*2*DM];
__device__ float g_part[SPLITS*MROWS*DM];      // unnormalized attention partials
__device__ float g_pstat[SPLITS*MROWS*4*2];    // per (split,row,head): m, s

// ---------------------------------------------------------------------------
__device__ __forceinline__ unsigned f2tf(float x){
    unsigned u; asm("cvt.rna.tf32.f32 %0,%1;" : "=r"(u) : "f"(x)); return u;
}
__device__ __forceinline__ void mma8(float* c, const unsigned* a, const unsigned* b){
    asm volatile("mma.sync.aligned.m16n8k8.row.col.f32.tf32.tf32.f32 "
        "{%0,%1,%2,%3},{%4,%5,%6,%7},{%8,%9},{%0,%1,%2,%3};"
        : "+f"(c[0]), "+f"(c[1]), "+f"(c[2]), "+f"(c[3])
        : "r"(a[0]), "r"(a[1]), "r"(a[2]), "r"(a[3]), "r"(b[0]), "r"(b[1]));
}
// e^x for x <= 0, FMA-pipe only. rel err ~2e-6.
__device__ __forceinline__ float fast_exp(float x){
    float y = x * 1.44269504f;
    y = fmaxf(y, -126.0f);
    float z = y + 12582912.0f;
    int   n = __float_as_int(z) - 0x4B400000;
    float f = y - (z - 12582912.0f);
    float p = 1.33336e-3f;
    p = fmaf(p, f, 9.61813e-3f);
    p = fmaf(p, f, 5.55041e-2f);
    p = fmaf(p, f, 2.40227e-1f);
    p = fmaf(p, f, 6.93147e-1f);
    p = fmaf(p, f, 1.0f);
    return p * __int_as_float((n + 127) << 23);
}

// ---------------------------------------------------------------------------
// tf32 GEMM: BM=32, BN=256, BK=32, 256 threads, double-buffered smem. (R4 proven)
// ---------------------------------------------------------------------------
#define AM_PLAIN 0
#define AM_ADD   1
#define AM_CAT   2
#define EPI_NONE 0
#define EPI_RELU 1
#define EPI_LN   2
#define EPI_LNR  3

#define AS_STR 36
#define BS_STR 264
#define BUF_WORDS (32*AS_STR + 32*BS_STR)
#define SM_GEMM (2*BUF_WORDS*4)

template<int KD, int AM>
__device__ __forceinline__ void gload(const float* __restrict__ A1, const float* __restrict__ A2,
    const float* __restrict__ B, int ldb, int n0, int row0, int kc, int tid,
    float4& pa, float4* pb)
{
    int ar = tid >> 3, ac4 = (tid & 7) << 2;
    int col = kc*32 + ac4;
    if (AM == AM_ADD){
        float4 x1 = *(const float4*)(A1 + (row0+ar)*KD + col);
        float4 x2 = *(const float4*)(A2 + (row0+ar)*KD + col);
        pa = make_float4(x1.x+x2.x, x1.y+x2.y, x1.z+x2.z, x1.w+x2.w);
    } else if (AM == AM_CAT){
        const float* s = (col < 256) ? (A1 + (row0+ar)*256 + col)
                                     : (A2 + (row0+ar)*256 + (col-256));
        pa = *(const float4*)s;
    } else {
        pa = *(const float4*)(A1 + (row0+ar)*KD + col);
    }
    #pragma unroll
    for (int i = 0; i < 8; i++){
        int id = tid + i*256;
        int r = id >> 6, c4 = (id & 63) << 2;
        pb[i] = *(const float4*)(B + (kc*32 + r)*ldb + n0 + c4);
    }
}

__device__ __forceinline__ void sstore(unsigned* Abuf, unsigned* Bbuf, int tid,
    const float4& pa, const float4* pb)
{
    int ar = tid >> 3, ac4 = (tid & 7) << 2;
    unsigned* d = &Abuf[ar*AS_STR + ac4];
    d[0]=f2tf(pa.x); d[1]=f2tf(pa.y); d[2]=f2tf(pa.z); d[3]=f2tf(pa.w);
    #pragma unroll
    for (int i = 0; i < 8; i++){
        int id = tid + i*256;
        int r = id >> 6, c4 = (id & 63) << 2;
        unsigned* e = &Bbuf[r*BS_STR + c4];
        e[0]=f2tf(pb[i].x); e[1]=f2tf(pb[i].y); e[2]=f2tf(pb[i].z); e[3]=f2tf(pb[i].w);
    }
}

template<int KD, int AM, int EPI>
__device__ __forceinline__ void gemm_body(
    const float* __restrict__ A1, const float* __restrict__ A2,
    const float* __restrict__ B, int ldb, int n0,
    const float* __restrict__ gamma, const float* __restrict__ beta,
    const float* __restrict__ resid, float* __restrict__ C, int ldc)
{
    extern __shared__ unsigned smu[];
    const int KC = KD/32;
    int tid = threadIdx.x;
    int w = tid >> 5, lane = tid & 31;
    int wm = w >> 2, wn = w & 3;
    int g4 = lane >> 2, tig = lane & 3;
    int row0 = blockIdx.x * 32;

    float acc[8][4];
    #pragma unroll
    for (int nt = 0; nt < 8; nt++)
        #pragma unroll
        for (int i = 0; i < 4; i++) acc[nt][i] = 0.f;

    float4 pa, pb[8];
    gload<KD, AM>(A1, A2, B, ldb, n0, row0, 0, tid, pa, pb);
    sstore(smu, smu + 32*AS_STR, tid, pa, pb);
    __syncthreads();

    for (int kc = 0; kc < KC; kc++){
        unsigned* Abuf = smu + (kc & 1)*BUF_WORDS;
        unsigned* Bbuf = Abuf + 32*AS_STR;
        if (kc + 1 < KC)
            gload<KD, AM>(A1, A2, B, ldb, n0, row0, kc+1, tid, pa, pb);
        #pragma unroll
        for (int kk = 0; kk < 4; kk++){
            int k0 = kk*8;
            unsigned a[4], bf[2];
            int r = wm*16 + g4;
            a[0] = Abuf[r*AS_STR + k0 + tig];
            a[1] = Abuf[(r+8)*AS_STR + k0 + tig];
            a[2] = Abuf[r*AS_STR + k0 + tig + 4];
            a[3] = Abuf[(r+8)*AS_STR + k0 + tig + 4];
            #pragma unroll
            for (int nt = 0; nt < 8; nt++){
                int n = wn*64 + nt*8 + g4;
                bf[0] = Bbuf[(k0 + tig)*BS_STR + n];
                bf[1] = Bbuf[(k0 + tig + 4)*BS_STR + n];
                mma8(acc[nt], a, bf);
            }
        }
        if (kc + 1 < KC){
            unsigned* An = smu + ((kc+1) & 1)*BUF_WORDS;
            sstore(An, An + 32*AS_STR, tid, pa, pb);
        }
        __syncthreads();
    }

    if (EPI == EPI_NONE || EPI == EPI_RELU){
        int rl = row0 + wm*16 + g4;
        #pragma unroll
        for (int nt = 0; nt < 8; nt++){
            int col = n0 + wn*64 + nt*8 + 2*tig;
            float v0 = acc[nt][0], v1 = acc[nt][1];
            float v2 = acc[nt][2], v3 = acc[nt][3];
            if (EPI == EPI_RELU){
                v0=fmaxf(v0,0.f); v1=fmaxf(v1,0.f); v2=fmaxf(v2,0.f); v3=fmaxf(v3,0.f);
            }
            *(float2*)(C + rl*ldc + col)     = make_float2(v0, v1);
            *(float2*)(C + (rl+8)*ldc + col) = make_float2(v2, v3);
        }
    } else {
        float2* red = (float2*)smu;
        float s1[2] = {0,0}, s2[2] = {0,0};
        #pragma unroll
        for (int nt = 0; nt < 8; nt++){
            float c0=acc[nt][0], c1=acc[nt][1], c2=acc[nt][2], c3=acc[nt][3];
            s1[0] += c0+c1; s2[0] += c0*c0 + c1*c1;
            s1[1] += c2+c3; s2[1] += c2*c2 + c3*c3;
        }
        #pragma unroll
        for (int hb = 0; hb < 2; hb++){
            float v1 = s1[hb], v2 = s2[hb];
            v1 += __shfl_xor_sync(~0u, v1, 1); v1 += __shfl_xor_sync(~0u, v1, 2);
            v2 += __shfl_xor_sync(~0u, v2, 1); v2 += __shfl_xor_sync(~0u, v2, 2);
            if (tig == 0){
                int r = wm*16 + g4 + hb*8;
                red[r*4 + wn] = make_float2(v1, v2);
            }
        }
        __syncthreads();
        #pragma unroll
        for (int hb = 0; hb < 2; hb++){
            int r = wm*16 + g4 + hb*8;
            float S1 = 0.f, S2 = 0.f;
            #pragma unroll
            for (int j = 0; j < 4; j++){ float2 e = red[r*4+j]; S1 += e.x; S2 += e.y; }
            float mean = S1 * (1.f/256.f);
            float var  = S2 * (1.f/256.f) - mean*mean;
            float inv  = rsqrtf(var + 1e-5f);
            int grow = row0 + r;
            #pragma unroll
            for (int nt = 0; nt < 8; nt++){
                int col = wn*64 + nt*8 + 2*tig;
                float c0 = acc[nt][hb*2], c1 = acc[nt][hb*2+1];
                float o0 = (c0 - mean)*inv*gamma[col]   + beta[col];
                float o1 = (c1 - mean)*inv*gamma[col+1] + beta[col+1];
                if (EPI == EPI_LNR){
                    o0 += resid[grow*256 + col];
                    o1 += resid[grow*256 + col + 1];
                }
                *(float2*)(C + grow*ldc + col) = make_float2(o0, o1);
            }
        }
    }
}

__global__ void __launch_bounds__(256) k_qkv(
    const float* x, const float* xpe, const float* src, const float* spe,
    const float* Wq, const float* Wk, const float* Wv)
{
    if (blockIdx.z == 0)      gemm_body<256, AM_ADD,   EPI_NONE>(x,   xpe, Wq, 256, 0, 0,0,0, g_Q, 256);
    else if (blockIdx.z == 1) gemm_body<256, AM_ADD,   EPI_NONE>(src, spe, Wk, 256, 0, 0,0,0, g_K, 256);
    else                      gemm_body<256, AM_PLAIN, EPI_NONE>(src, 0,   Wv, 256, 0, 0,0,0, g_V, 256);
}
__global__ void __launch_bounds__(256) k_merge(const float* Wmg, const float* gg, const float* bb){
    gemm_body<256, AM_PLAIN, EPI_LN>(g_O, 0, Wmg, 256, 0, gg, bb, 0, g_msg, 256);
}
__global__ void __launch_bounds__(256) k_mlp1(const float* x, const float* Wm1){
    gemm_body<512, AM_CAT, EPI_RELU>(x, g_msg, Wm1, 512, blockIdx.y*256, 0,0,0, g_hid, 512);
}
__global__ void __launch_bounds__(256) k_mlp2(const float* Wm2, const float* gg, const float* bb,
                                              const float* x, float* out){
    gemm_body<512, AM_PLAIN, EPI_LNR>(g_hid, 0, Wm2, 256, 0, gg, bb, x, out, 256);
}

// ---------------------------------------------------------------------------
// Flash attention v3. CTA = (32 l-rows, KV-split half, batch); all 4 heads,
// all 8 warps on the SAME 32-s tile. warp = (h = w&3, wm = w>>2): rows
// wm*16+(g4, g4+8), head h -> softmax fully warp-local. P overlays K smem.
// Partials (unnormalized o + m/s stats) to gmem; tiny merge kernel follows.
// smem 102 KB -> 2 CTAs/SM; grid 256 = 2 CTAs on each of 128 SMs, one wave.
// ---------------------------------------------------------------------------
#define QS_STR 260
#define KS_STR 260
#define VS_STR 264
#define PS_STR 36
#define CS_STR 33

#define AOF_KP   8320                     // K tile / P overlay
#define AOF_V    (AOF_KP + 8320)          // 16640
#define AOF_C    (AOF_V + 8448)           // 25088
#define AOF_SMS  (AOF_C + 1056)           // 26144
#define AOF_XM   (AOF_SMS + 32)           // 26176
#define ATTN_WORDS (AOF_XM + 32)          // 26208
#define SM_ATTN (ATTN_WORDS*4)            // 104832 bytes

__global__ void __launch_bounds__(256, 2) k_attn(
    const float* __restrict__ Qm, const float* __restrict__ Km, const float* __restrict__ Vm,
    const float* __restrict__ comp, const int* __restrict__ xmask, const int* __restrict__ smask)
{
    extern __shared__ float sm[];
    int tid = threadIdx.x;
    int w = tid >> 5, lane = tid & 31;
    int h = w & 3, wm = w >> 2;
    int g4 = lane >> 2, tig = lane & 3;
    int l0 = blockIdx.x * 32;
    int sp = blockIdx.y, b = blockIdx.z;
    int dbase = h*64;

    unsigned* Qs = (unsigned*)sm;
    unsigned* Ks = (unsigned*)sm + AOF_KP;
    unsigned* Pw = (unsigned*)sm + AOF_KP + h*1152;   // P[h]: 32 x 36, overlays K
    unsigned* Vs = (unsigned*)sm + AOF_V;
    float*    Cs = sm + AOF_C;
    int*      sms = (int*)(sm + AOF_SMS);
    int*      xm  = (int*)(sm + AOF_XM);

    // stage Q (32x256, tf32)
    #pragma unroll
    for (int i = 0; i < 8; i++){
        int id = tid + i*256;
        int r = id >> 6, c4 = (id & 63) << 2;
        float4 v = *(const float4*)(Qm + (b*LQ + l0 + r)*256 + c4);
        unsigned* d = &Qs[r*QS_STR + c4];
        d[0]=f2tf(v.x); d[1]=f2tf(v.y); d[2]=f2tf(v.z); d[3]=f2tf(v.w);
    }
    if (tid < 32) xm[tid] = xmask[b*LQ + l0 + tid];

    float o[8][4];
    #pragma unroll
    for (int nt = 0; nt < 8; nt++)
        #pragma unroll
        for (int i = 0; i < 4; i++) o[nt][i] = 0.f;
    float rmax[2] = {-1e30f, -1e30f};
    float rsum[2] = {0.f, 0.f};

    int rl = wm*16 + g4;     // low row in warp
    for (int t = 0; t < 1024/32; t++){
        int s0 = sp*(LQ/SPLITS) + t*32;
        __syncthreads();     // prev tile fully consumed (V, P reads done)
        // K, V tiles 32x256
        #pragma unroll
        for (int i = 0; i < 8; i++){
            int id = tid + i*256;
            int r = id >> 6, c4 = (id & 63) << 2;
            int grow = (b*LQ + s0 + r)*256 + c4;
            float4 vk = *(const float4*)(Km + grow);
            unsigned* dk = &Ks[r*KS_STR + c4];
            dk[0]=f2tf(vk.x); dk[1]=f2tf(vk.y); dk[2]=f2tf(vk.z); dk[3]=f2tf(vk.w);
            float4 vv = *(const float4*)(Vm + grow);
            unsigned* dv = &Vs[r*VS_STR + c4];
            dv[0]=f2tf(vv.x); dv[1]=f2tf(vv.y); dv[2]=f2tf(vv.z); dv[3]=f2tf(vv.w);
        }
        // comp tile 32x32, pre-scaled by 1/8
        {
            int r = tid >> 5, c = tid & 31;
            #pragma unroll
            for (int i = 0; i < 4; i++)
                Cs[(r + i*8)*CS_STR + c] = comp[(long)(b*LQ + l0 + r + i*8)*LQ + s0 + c] * 0.125f;
        }
        if (tid < 32) sms[tid] = smask[b*LQ + s0 + tid];
        __syncthreads();     // tiles ready

        // ---- QK^T: S[16l x 32s] per warp ----
        float S[4][4];
        #pragma unroll
        for (int nt = 0; nt < 4; nt++)
            #pragma unroll
            for (int i = 0; i < 4; i++) S[nt][i] = 0.f;
        #pragma unroll
        for (int kk = 0; kk < 8; kk++){
            int k0 = dbase + kk*8;
            unsigned a[4], bf[2];
            a[0] = Qs[rl*QS_STR + k0 + tig];
            a[1] = Qs[(rl+8)*QS_STR + k0 + tig];
            a[2] = Qs[rl*QS_STR + k0 + tig + 4];
            a[3] = Qs[(rl+8)*QS_STR + k0 + tig + 4];
            #pragma unroll
            for (int nt = 0; nt < 4; nt++){
                int s = nt*8 + g4;
                bf[0] = Ks[s*KS_STR + k0 + tig];
                bf[1] = Ks[s*KS_STR + k0 + tig + 4];
                mma8(S[nt], a, bf);
            }
        }
        __syncthreads();     // all K reads done before P overlays K

        // ---- softmax (warp-local rows) ----
        int xml = xm[rl], xmh = xm[rl + 8];
        float tmaxl = -1e30f, tmaxh = -1e30f;
        #pragma unroll
        for (int nt = 0; nt < 4; nt++){
            int se = nt*8 + 2*tig, so = se + 1;
            int mse = sms[se], mso = sms[so];
            float ce = Cs[rl*CS_STR + se],      co = Cs[rl*CS_STR + so];
            float de = Cs[(rl+8)*CS_STR + se],  dox = Cs[(rl+8)*CS_STR + so];
            float v0 = (xml && !mse) ? -1e30f : S[nt][0]*ce;
            float v1 = (xml && !mso) ? -1e30f : S[nt][1]*co;
            float v2 = (xmh && !mse) ? -1e30f : S[nt][2]*de;
            float v3 = (xmh && !mso) ? -1e30f : S[nt][3]*dox;
            S[nt][0]=v0; S[nt][1]=v1; S[nt][2]=v2; S[nt][3]=v3;
            tmaxl = fmaxf(tmaxl, fmaxf(v0, v1));
            tmaxh = fmaxf(tmaxh, fmaxf(v2, v3));
        }
        tmaxl = fmaxf(tmaxl, __shfl_xor_sync(~0u, tmaxl, 1));
        tmaxl = fmaxf(tmaxl, __shfl_xor_sync(~0u, tmaxl, 2));
        tmaxh = fmaxf(tmaxh, __shfl_xor_sync(~0u, tmaxh, 1));
        tmaxh = fmaxf(tmaxh, __shfl_xor_sync(~0u, tmaxh, 2));
        float ml = fmaxf(rmax[0], tmaxl), mh = fmaxf(rmax[1], tmaxh);
        float al = fast_exp(rmax[0] - ml), ah = fast_exp(rmax[1] - mh);
        rmax[0] = ml; rmax[1] = mh;
        float tsl = 0.f, tsh = 0.f;
        #pragma unroll
        for (int nt = 0; nt < 4; nt++){
            float p0 = fast_exp(S[nt][0] - ml);
            float p1 = fast_exp(S[nt][1] - ml);
            float p2 = fast_exp(S[nt][2] - mh);
            float p3 = fast_exp(S[nt][3] - mh);
            tsl += p0 + p1; tsh += p2 + p3;
            int se = nt*8 + 2*tig;
            *(uint2*)&Pw[rl*PS_STR + se]     = make_uint2(f2tf(p0), f2tf(p1));
            *(uint2*)&Pw[(rl+8)*PS_STR + se] = make_uint2(f2tf(p2), f2tf(p3));
        }
        tsl += __shfl_xor_sync(~0u, tsl, 1); tsl += __shfl_xor_sync(~0u, tsl, 2);
        tsh += __shfl_xor_sync(~0u, tsh, 1); tsh += __shfl_xor_sync(~0u, tsh, 2);
        rsum[0] = rsum[0]*al + tsl;
        rsum[1] = rsum[1]*ah + tsh;
        #pragma unroll
        for (int nt = 0; nt < 8; nt++){
            o[nt][0] *= al; o[nt][1] *= al;
            o[nt][2] *= ah; o[nt][3] *= ah;
        }
        __syncwarp();        // P producer == consumer (same warp)

        // ---- P @ V: o[16l x 64d] ----
        #pragma unroll
        for (int kk = 0; kk < 4; kk++){
            int k0 = kk*8;
            unsigned a[4], bf[2];
            a[0] = Pw[rl*PS_STR + k0 + tig];
            a[1] = Pw[(rl+8)*PS_STR + k0 + tig];
            a[2] = Pw[rl*PS_STR + k0 + tig + 4];
            a[3] = Pw[(rl+8)*PS_STR + k0 + tig + 4];
            #pragma unroll
            for (int nt = 0; nt < 8; nt++){
                int d = dbase + nt*8 + g4;
                bf[0] = Vs[(k0 + tig)*VS_STR + d];
                bf[1] = Vs[(k0 + tig + 4)*VS_STR + d];
                mma8(o[nt], a, bf);
            }
        }
    }

    // ---- write unnormalized partials + stats ----
    long prow = (long)(sp*MROWS + b*LQ + l0 + rl);
    #pragma unroll
    for (int nt = 0; nt < 8; nt++){
        int col = dbase + nt*8 + 2*tig;
        *(float2*)(g_part + prow*256 + col)     = make_float2(o[nt][0], o[nt][1]);
        *(float2*)(g_part + (prow+8)*256 + col) = make_float2(o[nt][2], o[nt][3]);
    }
    if (tig == 0){
        long base = (prow*4 + h)*2;
        g_pstat[base]   = rmax[0];
        g_pstat[base+1] = rsum[0];
        long baseh = ((prow+8)*4 + h)*2;
        g_pstat[baseh]   = rmax[1];
        g_pstat[baseh+1] = rsum[1];
    }
}

// merge the KV-split partials -> g_O
__global__ void __launch_bounds__(256) k_attnmerge(int dummy)
{
    int r = blockIdx.x;        // 0..MROWS-1
    int c = threadIdx.x;       // 0..255
    int h = c >> 6;
    float m0 = g_pstat[(((long)0*MROWS + r)*4 + h)*2];
    float s0 = g_pstat[(((long)0*MROWS + r)*4 + h)*2 + 1];
    float m1 = g_pstat[(((long)1*MROWS + r)*4 + h)*2];
    float s1 = g_pstat[(((long)1*MROWS + r)*4 + h)*2 + 1];
    float M = fmaxf(m0, m1);
    float w0 = fast_exp(m0 - M), w1 = fast_exp(m1 - M);
    float inv = 1.0f / (s0*w0 + s1*w1);
    float p0 = g_part[((long)0*MROWS + r)*256 + c];
    float p1 = g_part[((long)1*MROWS + r)*256 + c];
    g_O[(long)r*256 + c] = (p0*w0 + p1*w1) * inv;
}

// ---------------------------------------------------------------------------
extern "C" void kernel_launch(void* const* d_in, const int* in_sizes, int n_in,
                              void* d_out, int out_size)
{
    const float* x    = (const float*)d_in[0];
    const float* src  = (const float*)d_in[1];
    const float* xpe  = (const float*)d_in[2];
    const float* spe  = (const float*)d_in[3];
    const int* xmask  = (const int*)d_in[4];
    const int* smask  = (const int*)d_in[5];
    const float* comp = (const float*)d_in[6];
    const float* Wq   = (const float*)d_in[7];
    const float* Wk   = (const float*)d_in[8];
    const float* Wv   = (const float*)d_in[9];
    const float* Wmg  = (const float*)d_in[10];
    const float* Wm1  = (const float*)d_in[11];
    const float* Wm2  = (const float*)d_in[12];
    const float* ln1g = (const float*)d_in[13];
    const float* ln1b = (const float*)d_in[14];
    const float* ln2g = (const float*)d_in[15];
    const float* ln2b = (const float*)d_in[16];
    float* out = (float*)d_out;

    float *Qp, *Kp, *Vp;
    cudaGetSymbolAddress((void**)&Qp, g_Q);
    cudaGetSymbolAddress((void**)&Kp, g_K);
    cudaGetSymbolAddress((void**)&Vp, g_V);

    cudaFuncSetAttribute(k_qkv,   cudaFuncAttributeMaxDynamicSharedMemorySize, SM_GEMM);
    cudaFuncSetAttribute(k_merge, cudaFuncAttributeMaxDynamicSharedMemorySize, SM_GEMM);
    cudaFuncSetAttribute(k_mlp1,  cudaFuncAttributeMaxDynamicSharedMemorySize, SM_GEMM);
    cudaFuncSetAttribute(k_mlp2,  cudaFuncAttributeMaxDynamicSharedMemorySize, SM_GEMM);
    cudaFuncSetAttribute(k_attn,  cudaFuncAttributeMaxDynamicSharedMemorySize, SM_ATTN);

    k_qkv <<<dim3(MROWS/32, 1, 3), 256, SM_GEMM>>>(x, xpe, src, spe, Wq, Wk, Wv);
    k_attn<<<dim3(LQ/32, SPLITS, BSZ), 256, SM_ATTN>>>(Qp, Kp, Vp, comp, xmask, smask);
    k_attnmerge<<<MROWS, 256>>>(0);
    k_merge<<<MROWS/32,            256, SM_GEMM>>>(Wmg, ln1g, ln1b);
    k_mlp1<<<dim3(MROWS/32, 2),    256, SM_GEMM>>>(x, Wm1);
    k_mlp2<<<MROWS/32,             256, SM_GEMM>>>(Wm2, ln2g, ln2b, x, out);
}

// round 7
// speedup vs baseline: 2.4739x; 1.3971x over previous
#include <cuda_runtime.h>
#include <cuda_fp16.h>
#include <cstdint>

#define BSZ 2
#define LQ 2048
#define DM 256
#define MROWS (BSZ*LQ)
#define SPLITS 2

// scratch
__device__ float g_Q[MROWS*DM];
__device__ float g_K[MROWS*DM];
__device__ float g_V[MROWS*DM];
__device__ float g_O[MROWS*DM];
__device__ float g_msg[MROWS*DM];
__device__ float g_hid[MROWS*2*DM];
__device__ float g_part[SPLITS*MROWS*DM];
__device__ float g_pstat[SPLITS*MROWS*4*2];

// ---------------------------------------------------------------------------
__device__ __forceinline__ unsigned h2pk(float lo, float hi){
    unsigned r; asm("cvt.rn.f16x2.f32 %0, %1, %2;" : "=r"(r) : "f"(hi), "f"(lo)); return r;
}
__device__ __forceinline__ void ldsm4(unsigned* r, unsigned a){
    asm volatile("ldmatrix.sync.aligned.m8n8.x4.shared.b16 {%0,%1,%2,%3},[%4];"
        : "=r"(r[0]),"=r"(r[1]),"=r"(r[2]),"=r"(r[3]) : "r"(a));
}
__device__ __forceinline__ void ldsm4t(unsigned* r, unsigned a){
    asm volatile("ldmatrix.sync.aligned.m8n8.x4.trans.shared.b16 {%0,%1,%2,%3},[%4];"
        : "=r"(r[0]),"=r"(r[1]),"=r"(r[2]),"=r"(r[3]) : "r"(a));
}
__device__ __forceinline__ void mma16(float* c, const unsigned* a, const unsigned* b){
    asm volatile("mma.sync.aligned.m16n8k16.row.col.f32.f16.f16.f32 "
        "{%0,%1,%2,%3},{%4,%5,%6,%7},{%8,%9},{%0,%1,%2,%3};"
        : "+f"(c[0]), "+f"(c[1]), "+f"(c[2]), "+f"(c[3])
        : "r"(a[0]), "r"(a[1]), "r"(a[2]), "r"(a[3]), "r"(b[0]), "r"(b[1]));
}
// e^x for x <= 0, FMA-pipe only. rel err ~2e-6.
__device__ __forceinline__ float fast_exp(float x){
    float y = x * 1.44269504f;
    y = fmaxf(y, -126.0f);
    float z = y + 12582912.0f;
    int   n = __float_as_int(z) - 0x4B400000;
    float f = y - (z - 12582912.0f);
    float p = 1.33336e-3f;
    p = fmaf(p, f, 9.61813e-3f);
    p = fmaf(p, f, 5.55041e-2f);
    p = fmaf(p, f, 2.40227e-1f);
    p = fmaf(p, f, 6.93147e-1f);
    p = fmaf(p, f, 1.0f);
    return p * __int_as_float((n + 127) << 23);
}

// ---------------------------------------------------------------------------
// fp16 GEMM: BM=32, BN=256, BK=32, 256 threads, double-buffered smem,
// ldmatrix frag loads, m16n8k16 mma. Epilogues as before.
// ---------------------------------------------------------------------------
#define AM_PLAIN 0
#define AM_ADD   1
#define AM_CAT   2
#define EPI_NONE 0
#define EPI_RELU 1
#define EPI_LN   2
#define EPI_LNR  3

#define AS_H 40          // A tile stride (halves): 32+8
#define BS_H 264         // B tile stride (halves): 256+8
#define BUF_H (32*AS_H + 32*BS_H)   // 9728 halves
#define SM_GEMM (2*BUF_H*2)         // 38912 bytes

template<int KD, int AM>
__device__ __forceinline__ void gload(const float* __restrict__ A1, const float* __restrict__ A2,
    const float* __restrict__ B, int ldb, int n0, int row0, int kc, int tid,
    float4& pa, float4* pb)
{
    int ar = tid >> 3, ac4 = (tid & 7) << 2;
    int col = kc*32 + ac4;
    if (AM == AM_ADD){
        float4 x1 = *(const float4*)(A1 + (row0+ar)*KD + col);
        float4 x2 = *(const float4*)(A2 + (row0+ar)*KD + col);
        pa = make_float4(x1.x+x2.x, x1.y+x2.y, x1.z+x2.z, x1.w+x2.w);
    } else if (AM == AM_CAT){
        const float* s = (col < 256) ? (A1 + (row0+ar)*256 + col)
                                     : (A2 + (row0+ar)*256 + (col-256));
        pa = *(const float4*)s;
    } else {
        pa = *(const float4*)(A1 + (row0+ar)*KD + col);
    }
    #pragma unroll
    for (int i = 0; i < 8; i++){
        int id = tid + i*256;
        int r = id >> 6, c4 = (id & 63) << 2;
        pb[i] = *(const float4*)(B + (kc*32 + r)*ldb + n0 + c4);
    }
}

__device__ __forceinline__ void sstore_h(__half* buf, int tid, const float4& pa, const float4* pb)
{
    __half* Ab = buf;
    __half* Bb = buf + 32*AS_H;
    int ar = tid >> 3, ac4 = (tid & 7) << 2;
    *(uint2*)&Ab[ar*AS_H + ac4] = make_uint2(h2pk(pa.x, pa.y), h2pk(pa.z, pa.w));
    #pragma unroll
    for (int i = 0; i < 8; i++){
        int id = tid + i*256;
        int r = id >> 6, c4 = (id & 63) << 2;
        *(uint2*)&Bb[r*BS_H + c4] = make_uint2(h2pk(pb[i].x, pb[i].y), h2pk(pb[i].z, pb[i].w));
    }
}

template<int KD, int AM, int EPI>
__device__ __forceinline__ void gemm_body(
    const float* __restrict__ A1, const float* __restrict__ A2,
    const float* __restrict__ B, int ldb, int n0,
    const float* __restrict__ gamma, const float* __restrict__ beta,
    const float* __restrict__ resid, float* __restrict__ C, int ldc)
{
    extern __shared__ unsigned char smraw[];
    __half* smh = (__half*)smraw;
    const int KC = KD/32;
    int tid = threadIdx.x;
    int w = tid >> 5, lane = tid & 31;
    int wm = w >> 2, wn = w & 3;
    int g4 = lane >> 2, tig = lane & 3;
    int lrow = (lane & 7) + ((lane >> 3) & 1)*8;
    int lcol8 = (lane >> 4)*8;
    int row0 = blockIdx.x * 32;
    unsigned sb = (unsigned)__cvta_generic_to_shared(smh);

    float acc[8][4];
    #pragma unroll
    for (int nt = 0; nt < 8; nt++)
        #pragma unroll
        for (int i = 0; i < 4; i++) acc[nt][i] = 0.f;

    float4 pa, pb[8];
    gload<KD, AM>(A1, A2, B, ldb, n0, row0, 0, tid, pa, pb);
    sstore_h(smh, tid, pa, pb);
    __syncthreads();

    for (int kc = 0; kc < KC; kc++){
        unsigned ab = sb + ((kc & 1)*BUF_H)*2;
        unsigned bb = ab + 32*AS_H*2;
        if (kc + 1 < KC)
            gload<KD, AM>(A1, A2, B, ldb, n0, row0, kc+1, tid, pa, pb);
        #pragma unroll
        for (int kk = 0; kk < 2; kk++){
            int k0 = kk*16;
            unsigned a[4];
            ldsm4(a, ab + ((wm*16 + lrow)*AS_H + k0 + lcol8)*2);
            #pragma unroll
            for (int j = 0; j < 4; j++){
                unsigned bv[4];
                ldsm4t(bv, bb + ((k0 + lrow)*BS_H + wn*64 + j*16 + lcol8)*2);
                unsigned b0[2] = {bv[0], bv[1]};
                unsigned b1[2] = {bv[2], bv[3]};
                mma16(acc[2*j],   a, b0);
                mma16(acc[2*j+1], a, b1);
            }
        }
        if (kc + 1 < KC)
            sstore_h(smh + ((kc+1) & 1)*BUF_H, tid, pa, pb);
        __syncthreads();
    }

    if (EPI == EPI_NONE || EPI == EPI_RELU){
        int rl = row0 + wm*16 + g4;
        #pragma unroll
        for (int nt = 0; nt < 8; nt++){
            int col = n0 + wn*64 + nt*8 + 2*tig;
            float v0 = acc[nt][0], v1 = acc[nt][1];
            float v2 = acc[nt][2], v3 = acc[nt][3];
            if (EPI == EPI_RELU){
                v0=fmaxf(v0,0.f); v1=fmaxf(v1,0.f); v2=fmaxf(v2,0.f); v3=fmaxf(v3,0.f);
            }
            *(float2*)(C + rl*ldc + col)     = make_float2(v0, v1);
            *(float2*)(C + (rl+8)*ldc + col) = make_float2(v2, v3);
        }
    } else {
        float2* red = (float2*)smraw;    // red[32][4]
        float s1[2] = {0,0}, s2[2] = {0,0};
        #pragma unroll
        for (int nt = 0; nt < 8; nt++){
            float c0=acc[nt][0], c1=acc[nt][1], c2=acc[nt][2], c3=acc[nt][3];
            s1[0] += c0+c1; s2[0] += c0*c0 + c1*c1;
            s1[1] += c2+c3; s2[1] += c2*c2 + c3*c3;
        }
        #pragma unroll
        for (int hb = 0; hb < 2; hb++){
            float v1 = s1[hb], v2 = s2[hb];
            v1 += __shfl_xor_sync(~0u, v1, 1); v1 += __shfl_xor_sync(~0u, v1, 2);
            v2 += __shfl_xor_sync(~0u, v2, 1); v2 += __shfl_xor_sync(~0u, v2, 2);
            if (tig == 0){
                int r = wm*16 + g4 + hb*8;
                red[r*4 + wn] = make_float2(v1, v2);
            }
        }
        __syncthreads();
        #pragma unroll
        for (int hb = 0; hb < 2; hb++){
            int r = wm*16 + g4 + hb*8;
            float S1 = 0.f, S2 = 0.f;
            #pragma unroll
            for (int j = 0; j < 4; j++){ float2 e = red[r*4+j]; S1 += e.x; S2 += e.y; }
            float mean = S1 * (1.f/256.f);
            float var  = S2 * (1.f/256.f) - mean*mean;
            float inv  = rsqrtf(var + 1e-5f);
            int grow = row0 + r;
            #pragma unroll
            for (int nt = 0; nt < 8; nt++){
                int col = wn*64 + nt*8 + 2*tig;
                float c0 = acc[nt][hb*2], c1 = acc[nt][hb*2+1];
                float o0 = (c0 - mean)*inv*gamma[col]   + beta[col];
                float o1 = (c1 - mean)*inv*gamma[col+1] + beta[col+1];
                if (EPI == EPI_LNR){
                    o0 += resid[grow*256 + col];
                    o1 += resid[grow*256 + col + 1];
                }
                *(float2*)(C + grow*ldc + col) = make_float2(o0, o1);
            }
        }
    }
}

__global__ void __launch_bounds__(256) k_qkv(
    const float* x, const float* xpe, const float* src, const float* spe,
    const float* Wq, const float* Wk, const float* Wv)
{
    if (blockIdx.z == 0)      gemm_body<256, AM_ADD,   EPI_NONE>(x,   xpe, Wq, 256, 0, 0,0,0, g_Q, 256);
    else if (blockIdx.z == 1) gemm_body<256, AM_ADD,   EPI_NONE>(src, spe, Wk, 256, 0, 0,0,0, g_K, 256);
    else                      gemm_body<256, AM_PLAIN, EPI_NONE>(src, 0,   Wv, 256, 0, 0,0,0, g_V, 256);
}
__global__ void __launch_bounds__(256) k_merge(const float* Wmg, const float* gg, const float* bb){
    gemm_body<256, AM_PLAIN, EPI_LN>(g_O, 0, Wmg, 256, 0, gg, bb, 0, g_msg, 256);
}
__global__ void __launch_bounds__(256) k_mlp1(const float* x, const float* Wm1){
    gemm_body<512, AM_CAT, EPI_RELU>(x, g_msg, Wm1, 512, blockIdx.y*256, 0,0,0, g_hid, 512);
}
__global__ void __launch_bounds__(256) k_mlp2(const float* Wm2, const float* gg, const float* bb,
                                              const float* x, float* out){
    gemm_body<512, AM_PLAIN, EPI_LNR>(g_hid, 0, Wm2, 256, 0, gg, bb, x, out, 256);
}

// ---------------------------------------------------------------------------
// Flash attention v4 (fp16 mma). Structure = R6 v3: CTA = (32 l, split, b),
// all 4 heads, 8 warps on same s-tile; warp = (h=w&3, wm=w>>2). P overlays K.
// ---------------------------------------------------------------------------
#define QH 264                    // Q/K/V smem stride (halves)
#define PH 40                     // P stride (halves)
#define AT_K   8448               // half offsets
#define AT_V   16896
#define AT_CB  50688              // byte offset of Cs (= 25344 halves * 2)
#define CS_STR 33
#define ATTN_BYTES (AT_CB + 1056*4 + 64*4)   // 55168

__global__ void __launch_bounds__(256, 2) k_attn(
    const float* __restrict__ Qm, const float* __restrict__ Km, const float* __restrict__ Vm,
    const float* __restrict__ comp, const int* __restrict__ xmask, const int* __restrict__ smask)
{
    extern __shared__ unsigned char smraw[];
    __half* smh = (__half*)smraw;
    __half* Qh = smh;
    __half* Kh = smh + AT_K;
    __half* Vh = smh + AT_V;
    float*  Cs = (float*)(smraw + AT_CB);
    int*    sms = (int*)(smraw + AT_CB + 1056*4);
    int*    xm  = sms + 32;

    int tid = threadIdx.x;
    int w = tid >> 5, lane = tid & 31;
    int h = w & 3, wm = w >> 2;
    int g4 = lane >> 2, tig = lane & 3;
    int lrow = (lane & 7) + ((lane >> 3) & 1)*8;
    int lcol8 = (lane >> 4)*8;
    int l0 = blockIdx.x * 32;
    int sp = blockIdx.y, b = blockIdx.z;
    int dbase = h*64;

    unsigned sb = (unsigned)__cvta_generic_to_shared(smh);
    unsigned qb = sb;
    unsigned kb = sb + AT_K*2;
    unsigned vb = sb + AT_V*2;
    unsigned pbsu = sb + (AT_K + h*1280)*2;    // P[h] overlays K region
    __half* Ph = Kh + h*1280;

    // stage Q (32x256 -> half)
    #pragma unroll
    for (int i = 0; i < 8; i++){
        int id = tid + i*256;
        int r = id >> 6, c4 = (id & 63) << 2;
        float4 v = *(const float4*)(Qm + (b*LQ + l0 + r)*256 + c4);
        *(uint2*)&Qh[r*QH + c4] = make_uint2(h2pk(v.x, v.y), h2pk(v.z, v.w));
    }
    if (tid < 32) xm[tid] = xmask[b*LQ + l0 + tid];

    float o[8][4];
    #pragma unroll
    for (int nt = 0; nt < 8; nt++)
        #pragma unroll
        for (int i = 0; i < 4; i++) o[nt][i] = 0.f;
    float rmax[2] = {-1e30f, -1e30f};
    float rsum[2] = {0.f, 0.f};

    int rl = wm*16 + g4;
    for (int t = 0; t < (LQ/SPLITS)/32; t++){
        int s0 = sp*(LQ/SPLITS) + t*32;
        __syncthreads();     // prev tile fully consumed
        // K, V tiles 32x256 -> half
        #pragma unroll
        for (int i = 0; i < 8; i++){
            int id = tid + i*256;
            int r = id >> 6, c4 = (id & 63) << 2;
            int grow = (b*LQ + s0 + r)*256 + c4;
            float4 vk = *(const float4*)(Km + grow);
            *(uint2*)&Kh[r*QH + c4] = make_uint2(h2pk(vk.x, vk.y), h2pk(vk.z, vk.w));
            float4 vv = *(const float4*)(Vm + grow);
            *(uint2*)&Vh[r*QH + c4] = make_uint2(h2pk(vv.x, vv.y), h2pk(vv.z, vv.w));
        }
        // comp tile 32x32, pre-scaled by 1/8
        {
            int r = tid >> 5, c = tid & 31;
            #pragma unroll
            for (int i = 0; i < 4; i++)
                Cs[(r + i*8)*CS_STR + c] = comp[(long)(b*LQ + l0 + r + i*8)*LQ + s0 + c] * 0.125f;
        }
        if (tid < 32) sms[tid] = smask[b*LQ + s0 + tid];
        __syncthreads();     // tiles ready

        // ---- QK^T: S[16l x 32s] per warp (fp16 mma) ----
        float S[4][4];
        #pragma unroll
        for (int nt = 0; nt < 4; nt++)
            #pragma unroll
            for (int i = 0; i < 4; i++) S[nt][i] = 0.f;
        #pragma unroll
        for (int kk = 0; kk < 4; kk++){
            int k0 = dbase + kk*16;
            unsigned a[4];
            ldsm4(a, qb + ((wm*16 + lrow)*QH + k0 + lcol8)*2);
            #pragma unroll
            for (int sh = 0; sh < 2; sh++){
                unsigned bk[4];
                ldsm4(bk, kb + ((sh*16 + lrow)*QH + k0 + lcol8)*2);
                unsigned b0[2] = {bk[0], bk[2]};
                unsigned b1[2] = {bk[1], bk[3]};
                mma16(S[sh*2],   a, b0);
                mma16(S[sh*2+1], a, b1);
            }
        }
        __syncthreads();     // all K reads done before P overlays K

        // ---- softmax (warp-local rows) ----
        int xml = xm[rl], xmh = xm[rl + 8];
        float tmaxl = -1e30f, tmaxh = -1e30f;
        #pragma unroll
        for (int nt = 0; nt < 4; nt++){
            int se = nt*8 + 2*tig, so = se + 1;
            int mse = sms[se], mso = sms[so];
            float ce = Cs[rl*CS_STR + se],      co = Cs[rl*CS_STR + so];
            float de = Cs[(rl+8)*CS_STR + se],  dox = Cs[(rl+8)*CS_STR + so];
            float v0 = (xml && !mse) ? -1e30f : S[nt][0]*ce;
            float v1 = (xml && !mso) ? -1e30f : S[nt][1]*co;
            float v2 = (xmh && !mse) ? -1e30f : S[nt][2]*de;
            float v3 = (xmh && !mso) ? -1e30f : S[nt][3]*dox;
            S[nt][0]=v0; S[nt][1]=v1; S[nt][2]=v2; S[nt][3]=v3;
            tmaxl = fmaxf(tmaxl, fmaxf(v0, v1));
            tmaxh = fmaxf(tmaxh, fmaxf(v2, v3));
        }
        tmaxl = fmaxf(tmaxl, __shfl_xor_sync(~0u, tmaxl, 1));
        tmaxl = fmaxf(tmaxl, __shfl_xor_sync(~0u, tmaxl, 2));
        tmaxh = fmaxf(tmaxh, __shfl_xor_sync(~0u, tmaxh, 1));
        tmaxh = fmaxf(tmaxh, __shfl_xor_sync(~0u, tmaxh, 2));
        float ml = fmaxf(rmax[0], tmaxl), mh = fmaxf(rmax[1], tmaxh);
        float al = fast_exp(rmax[0] - ml), ah = fast_exp(rmax[1] - mh);
        rmax[0] = ml; rmax[1] = mh;
        float tsl = 0.f, tsh = 0.f;
        #pragma unroll
        for (int nt = 0; nt < 4; nt++){
            float p0 = fast_exp(S[nt][0] - ml);
            float p1 = fast_exp(S[nt][1] - ml);
            float p2 = fast_exp(S[nt][2] - mh);
            float p3 = fast_exp(S[nt][3] - mh);
            tsl += p0 + p1; tsh += p2 + p3;
            int se = nt*8 + 2*tig;
            *(unsigned*)&Ph[rl*PH + se]     = h2pk(p0, p1);
            *(unsigned*)&Ph[(rl+8)*PH + se] = h2pk(p2, p3);
        }
        tsl += __shfl_xor_sync(~0u, tsl, 1); tsl += __shfl_xor_sync(~0u, tsl, 2);
        tsh += __shfl_xor_sync(~0u, tsh, 1); tsh += __shfl_xor_sync(~0u, tsh, 2);
        rsum[0] = rsum[0]*al + tsl;
        rsum[1] = rsum[1]*ah + tsh;
        #pragma unroll
        for (int nt = 0; nt < 8; nt++){
            o[nt][0] *= al; o[nt][1] *= al;
            o[nt][2] *= ah; o[nt][3] *= ah;
        }
        __syncwarp();        // P producer == consumer (same warp)

        // ---- P @ V: o[16l x 64d] (fp16 mma, V via ldmatrix.trans) ----
        #pragma unroll
        for (int kk = 0; kk < 2; kk++){
            unsigned a[4];
            ldsm4(a, pbsu + ((wm*16 + lrow)*PH + kk*16 + lcol8)*2);
            #pragma unroll
            for (int j = 0; j < 4; j++){
                unsigned bv[4];
                ldsm4t(bv, vb + ((kk*16 + lrow)*QH + dbase + j*16 + lcol8)*2);
                unsigned b0[2] = {bv[0], bv[1]};
                unsigned b1[2] = {bv[2], bv[3]};
                mma16(o[2*j],   a, b0);
                mma16(o[2*j+1], a, b1);
            }
        }
    }

    // ---- write unnormalized partials + stats ----
    long prow = (long)(sp*MROWS + b*LQ + l0 + rl);
    #pragma unroll
    for (int nt = 0; nt < 8; nt++){
        int col = dbase + nt*8 + 2*tig;
        *(float2*)(g_part + prow*256 + col)     = make_float2(o[nt][0], o[nt][1]);
        *(float2*)(g_part + (prow+8)*256 + col) = make_float2(o[nt][2], o[nt][3]);
    }
    if (tig == 0){
        long base = (prow*4 + h)*2;
        g_pstat[base]   = rmax[0];
        g_pstat[base+1] = rsum[0];
        long baseh = ((prow+8)*4 + h)*2;
        g_pstat[baseh]   = rmax[1];
        g_pstat[baseh+1] = rsum[1];
    }
}

// merge the KV-split partials -> g_O
__global__ void __launch_bounds__(256) k_attnmerge(int dummy)
{
    int r = blockIdx.x;
    int c = threadIdx.x;
    int h = c >> 6;
    float m0 = g_pstat[(((long)0*MROWS + r)*4 + h)*2];
    float s0 = g_pstat[(((long)0*MROWS + r)*4 + h)*2 + 1];
    float m1 = g_pstat[(((long)1*MROWS + r)*4 + h)*2];
    float s1 = g_pstat[(((long)1*MROWS + r)*4 + h)*2 + 1];
    float M = fmaxf(m0, m1);
    float w0 = fast_exp(m0 - M), w1 = fast_exp(m1 - M);
    float inv = 1.0f / (s0*w0 + s1*w1);
    float p0 = g_part[((long)0*MROWS + r)*256 + c];
    float p1 = g_part[((long)1*MROWS + r)*256 + c];
    g_O[(long)r*256 + c] = (p0*w0 + p1*w1) * inv;
}

// ---------------------------------------------------------------------------
extern "C" void kernel_launch(void* const* d_in, const int* in_sizes, int n_in,
                              void* d_out, int out_size)
{
    const float* x    = (const float*)d_in[0];
    const float* src  = (const float*)d_in[1];
    const float* xpe  = (const float*)d_in[2];
    const float* spe  = (const float*)d_in[3];
    const int* xmask  = (const int*)d_in[4];
    const int* smask  = (const int*)d_in[5];
    const float* comp = (const float*)d_in[6];
    const float* Wq   = (const float*)d_in[7];
    const float* Wk   = (const float*)d_in[8];
    const float* Wv   = (const float*)d_in[9];
    const float* Wmg  = (const float*)d_in[10];
    const float* Wm1  = (const float*)d_in[11];
    const float* Wm2  = (const float*)d_in[12];
    const float* ln1g = (const float*)d_in[13];
    const float* ln1b = (const float*)d_in[14];
    const float* ln2g = (const float*)d_in[15];
    const float* ln2b = (const float*)d_in[16];
    float* out = (float*)d_out;

    float *Qp, *Kp, *Vp;
    cudaGetSymbolAddress((void**)&Qp, g_Q);
    cudaGetSymbolAddress((void**)&Kp, g_K);
    cudaGetSymbolAddress((void**)&Vp, g_V);

    cudaFuncSetAttribute(k_attn, cudaFuncAttributeMaxDynamicSharedMemorySize, ATTN_BYTES);

    k_qkv <<<dim3(MROWS/32, 1, 3), 256, SM_GEMM>>>(x, xpe, src, spe, Wq, Wk, Wv);
    k_attn<<<dim3(LQ/32, SPLITS, BSZ), 256, ATTN_BYTES>>>(Qp, Kp, Vp, comp, xmask, smask);
    k_attnmerge<<<MROWS, 256>>>(0);
    k_merge<<<MROWS/32,            256, SM_GEMM>>>(Wmg, ln1g, ln1b);
    k_mlp1<<<dim3(MROWS/32, 2),    256, SM_GEMM>>>(x, Wm1);
    k_mlp2<<<MROWS/32,             256, SM_GEMM>>>(Wm2, ln2g, ln2b, x, out);
}

// round 8
// speedup vs baseline: 2.7067x; 1.0941x over previous
#include <cuda_runtime.h>
#include <cuda_fp16.h>
#include <cstdint>

#define BSZ 2
#define LQ 2048
#define DM 256
#define MROWS (BSZ*LQ)
#define SPLITS 2

// scratch
__device__ __half g_Qh[MROWS*DM];
__device__ __half g_Kh[MROWS*DM];
__device__ __half g_Vh[MROWS*DM];
__device__ float g_O[MROWS*DM];
__device__ float g_msg[MROWS*DM];
__device__ float g_hid[MROWS*2*DM];
__device__ float g_part[SPLITS*MROWS*DM];
__device__ float g_pstat[SPLITS*MROWS*4*2];

// ---------------------------------------------------------------------------
__device__ __forceinline__ unsigned h2pk(float lo, float hi){
    unsigned r; asm("cvt.rn.f16x2.f32 %0, %1, %2;" : "=r"(r) : "f"(hi), "f"(lo)); return r;
}
__device__ __forceinline__ void ldsm4(unsigned* r, unsigned a){
    asm volatile("ldmatrix.sync.aligned.m8n8.x4.shared.b16 {%0,%1,%2,%3},[%4];"
        : "=r"(r[0]),"=r"(r[1]),"=r"(r[2]),"=r"(r[3]) : "r"(a));
}
__device__ __forceinline__ void ldsm4t(unsigned* r, unsigned a){
    asm volatile("ldmatrix.sync.aligned.m8n8.x4.trans.shared.b16 {%0,%1,%2,%3},[%4];"
        : "=r"(r[0]),"=r"(r[1]),"=r"(r[2]),"=r"(r[3]) : "r"(a));
}
__device__ __forceinline__ void mma16(float* c, const unsigned* a, const unsigned* b){
    asm volatile("mma.sync.aligned.m16n8k16.row.col.f32.f16.f16.f32 "
        "{%0,%1,%2,%3},{%4,%5,%6,%7},{%8,%9},{%0,%1,%2,%3};"
        : "+f"(c[0]), "+f"(c[1]), "+f"(c[2]), "+f"(c[3])
        : "r"(a[0]), "r"(a[1]), "r"(a[2]), "r"(a[3]), "r"(b[0]), "r"(b[1]));
}
// e^x for x <= 0, FMA-pipe only. rel err ~2e-6.
__device__ __forceinline__ float fast_exp(float x){
    float y = x * 1.44269504f;
    y = fmaxf(y, -126.0f);
    float z = y + 12582912.0f;
    int   n = __float_as_int(z) - 0x4B400000;
    float f = y - (z - 12582912.0f);
    float p = 1.33336e-3f;
    p = fmaf(p, f, 9.61813e-3f);
    p = fmaf(p, f, 5.55041e-2f);
    p = fmaf(p, f, 2.40227e-1f);
    p = fmaf(p, f, 6.93147e-1f);
    p = fmaf(p, f, 1.0f);
    return p * __int_as_float((n + 127) << 23);
}

// ---------------------------------------------------------------------------
// fp16 GEMM: BM=32, BN=256, BK=32, 256 threads, double-buffered smem,
// ldmatrix frag loads, m16n8k16 mma.
// ---------------------------------------------------------------------------
#define AM_PLAIN 0
#define AM_ADD   1
#define AM_CAT   2
#define EPI_NONE 0
#define EPI_RELU 1
#define EPI_LN   2
#define EPI_LNR  3
#define EPI_H16  4

#define AS_H 40
#define BS_H 264
#define BUF_H (32*AS_H + 32*BS_H)
#define SM_GEMM (2*BUF_H*2)

template<int KD, int AM>
__device__ __forceinline__ void gload(const float* __restrict__ A1, const float* __restrict__ A2,
    const float* __restrict__ B, int ldb, int n0, int row0, int kc, int tid,
    float4& pa, float4* pb)
{
    int ar = tid >> 3, ac4 = (tid & 7) << 2;
    int col = kc*32 + ac4;
    if (AM == AM_ADD){
        float4 x1 = *(const float4*)(A1 + (row0+ar)*KD + col);
        float4 x2 = *(const float4*)(A2 + (row0+ar)*KD + col);
        pa = make_float4(x1.x+x2.x, x1.y+x2.y, x1.z+x2.z, x1.w+x2.w);
    } else if (AM == AM_CAT){
        const float* s = (col < 256) ? (A1 + (row0+ar)*256 + col)
                                     : (A2 + (row0+ar)*256 + (col-256));
        pa = *(const float4*)s;
    } else {
        pa = *(const float4*)(A1 + (row0+ar)*KD + col);
    }
    #pragma unroll
    for (int i = 0; i < 8; i++){
        int id = tid + i*256;
        int r = id >> 6, c4 = (id & 63) << 2;
        pb[i] = *(const float4*)(B + (kc*32 + r)*ldb + n0 + c4);
    }
}

__device__ __forceinline__ void sstore_h(__half* buf, int tid, const float4& pa, const float4* pb)
{
    __half* Ab = buf;
    __half* Bb = buf + 32*AS_H;
    int ar = tid >> 3, ac4 = (tid & 7) << 2;
    *(uint2*)&Ab[ar*AS_H + ac4] = make_uint2(h2pk(pa.x, pa.y), h2pk(pa.z, pa.w));
    #pragma unroll
    for (int i = 0; i < 8; i++){
        int id = tid + i*256;
        int r = id >> 6, c4 = (id & 63) << 2;
        *(uint2*)&Bb[r*BS_H + c4] = make_uint2(h2pk(pb[i].x, pb[i].y), h2pk(pb[i].z, pb[i].w));
    }
}

template<int KD, int AM, int EPI>
__device__ __forceinline__ void gemm_body(
    const float* __restrict__ A1, const float* __restrict__ A2,
    const float* __restrict__ B, int ldb, int n0,
    const float* __restrict__ gamma, const float* __restrict__ beta,
    const float* __restrict__ resid, void* __restrict__ Cv, int ldc)
{
    extern __shared__ unsigned char smraw[];
    __half* smh = (__half*)smraw;
    const int KC = KD/32;
    int tid = threadIdx.x;
    int w = tid >> 5, lane = tid & 31;
    int wm = w >> 2, wn = w & 3;
    int g4 = lane >> 2, tig = lane & 3;
    int lrow = (lane & 7) + ((lane >> 3) & 1)*8;
    int lcol8 = (lane >> 4)*8;
    int row0 = blockIdx.x * 32;
    unsigned sb = (unsigned)__cvta_generic_to_shared(smh);

    float acc[8][4];
    #pragma unroll
    for (int nt = 0; nt < 8; nt++)
        #pragma unroll
        for (int i = 0; i < 4; i++) acc[nt][i] = 0.f;

    float4 pa, pb[8];
    gload<KD, AM>(A1, A2, B, ldb, n0, row0, 0, tid, pa, pb);
    sstore_h(smh, tid, pa, pb);
    __syncthreads();

    for (int kc = 0; kc < KC; kc++){
        unsigned ab = sb + ((kc & 1)*BUF_H)*2;
        unsigned bb = ab + 32*AS_H*2;
        if (kc + 1 < KC)
            gload<KD, AM>(A1, A2, B, ldb, n0, row0, kc+1, tid, pa, pb);
        #pragma unroll
        for (int kk = 0; kk < 2; kk++){
            int k0 = kk*16;
            unsigned a[4];
            ldsm4(a, ab + ((wm*16 + lrow)*AS_H + k0 + lcol8)*2);
            #pragma unroll
            for (int j = 0; j < 4; j++){
                unsigned bv[4];
                ldsm4t(bv, bb + ((k0 + lrow)*BS_H + wn*64 + j*16 + lcol8)*2);
                unsigned b0[2] = {bv[0], bv[1]};
                unsigned b1[2] = {bv[2], bv[3]};
                mma16(acc[2*j],   a, b0);
                mma16(acc[2*j+1], a, b1);
            }
        }
        if (kc + 1 < KC)
            sstore_h(smh + ((kc+1) & 1)*BUF_H, tid, pa, pb);
        __syncthreads();
    }

    if (EPI == EPI_H16){
        __half* C = (__half*)Cv;
        int rl = row0 + wm*16 + g4;
        #pragma unroll
        for (int nt = 0; nt < 8; nt++){
            int col = n0 + wn*64 + nt*8 + 2*tig;
            *(unsigned*)(C + rl*ldc + col)     = h2pk(acc[nt][0], acc[nt][1]);
            *(unsigned*)(C + (rl+8)*ldc + col) = h2pk(acc[nt][2], acc[nt][3]);
        }
    } else if (EPI == EPI_NONE || EPI == EPI_RELU){
        float* C = (float*)Cv;
        int rl = row0 + wm*16 + g4;
        #pragma unroll
        for (int nt = 0; nt < 8; nt++){
            int col = n0 + wn*64 + nt*8 + 2*tig;
            float v0 = acc[nt][0], v1 = acc[nt][1];
            float v2 = acc[nt][2], v3 = acc[nt][3];
            if (EPI == EPI_RELU){
                v0=fmaxf(v0,0.f); v1=fmaxf(v1,0.f); v2=fmaxf(v2,0.f); v3=fmaxf(v3,0.f);
            }
            *(float2*)(C + rl*ldc + col)     = make_float2(v0, v1);
            *(float2*)(C + (rl+8)*ldc + col) = make_float2(v2, v3);
        }
    } else {
        float* C = (float*)Cv;
        float2* red = (float2*)smraw;
        float s1[2] = {0,0}, s2[2] = {0,0};
        #pragma unroll
        for (int nt = 0; nt < 8; nt++){
            float c0=acc[nt][0], c1=acc[nt][1], c2=acc[nt][2], c3=acc[nt][3];
            s1[0] += c0+c1; s2[0] += c0*c0 + c1*c1;
            s1[1] += c2+c3; s2[1] += c2*c2 + c3*c3;
        }
        #pragma unroll
        for (int hb = 0; hb < 2; hb++){
            float v1 = s1[hb], v2 = s2[hb];
            v1 += __shfl_xor_sync(~0u, v1, 1); v1 += __shfl_xor_sync(~0u, v1, 2);
            v2 += __shfl_xor_sync(~0u, v2, 1); v2 += __shfl_xor_sync(~0u, v2, 2);
            if (tig == 0){
                int r = wm*16 + g4 + hb*8;
                red[r*4 + wn] = make_float2(v1, v2);
            }
        }
        __syncthreads();
        #pragma unroll
        for (int hb = 0; hb < 2; hb++){
            int r = wm*16 + g4 + hb*8;
            float S1 = 0.f, S2 = 0.f;
            #pragma unroll
            for (int j = 0; j < 4; j++){ float2 e = red[r*4+j]; S1 += e.x; S2 += e.y; }
            float mean = S1 * (1.f/256.f);
            float var  = S2 * (1.f/256.f) - mean*mean;
            float inv  = rsqrtf(var + 1e-5f);
            int grow = row0 + r;
            #pragma unroll
            for (int nt = 0; nt < 8; nt++){
                int col = wn*64 + nt*8 + 2*tig;
                float c0 = acc[nt][hb*2], c1 = acc[nt][hb*2+1];
                float o0 = (c0 - mean)*inv*gamma[col]   + beta[col];
                float o1 = (c1 - mean)*inv*gamma[col+1] + beta[col+1];
                if (EPI == EPI_LNR){
                    o0 += resid[grow*256 + col];
                    o1 += resid[grow*256 + col + 1];
                }
                *(float2*)(C + grow*ldc + col) = make_float2(o0, o1);
            }
        }
    }
}

__global__ void __launch_bounds__(256) k_qkv(
    const float* x, const float* xpe, const float* src, const float* spe,
    const float* Wq, const float* Wk, const float* Wv)
{
    if (blockIdx.z == 0)      gemm_body<256, AM_ADD,   EPI_H16>(x,   xpe, Wq, 256, 0, 0,0,0, g_Qh, 256);
    else if (blockIdx.z == 1) gemm_body<256, AM_ADD,   EPI_H16>(src, spe, Wk, 256, 0, 0,0,0, g_Kh, 256);
    else                      gemm_body<256, AM_PLAIN, EPI_H16>(src, 0,   Wv, 256, 0, 0,0,0, g_Vh, 256);
}
__global__ void __launch_bounds__(256) k_merge(const float* Wmg, const float* gg, const float* bb){
    gemm_body<256, AM_PLAIN, EPI_LN>(g_O, 0, Wmg, 256, 0, gg, bb, 0, g_msg, 256);
}
__global__ void __launch_bounds__(256) k_mlp1(const float* x, const float* Wm1){
    gemm_body<512, AM_CAT, EPI_RELU>(x, g_msg, Wm1, 512, blockIdx.y*256, 0,0,0, g_hid, 512);
}
__global__ void __launch_bounds__(256) k_mlp2(const float* Wm2, const float* gg, const float* bb,
                                              const float* x, float* out){
    gemm_body<512, AM_PLAIN, EPI_LNR>(g_hid, 0, Wm2, 256, 0, gg, bb, x, out, 256);
}

// ---------------------------------------------------------------------------
// Flash attention v5: same structure as R7, but Q/K/V are fp16 in gmem ->
// uint4 copies, no conversions, half the L2 traffic.
// ---------------------------------------------------------------------------
#define QH 264
#define PH 40
#define AT_K   8448
#define AT_V   16896
#define AT_CB  50688
#define CS_STR 33
#define ATTN_BYTES (AT_CB + 1056*4 + 64*4)

__global__ void __launch_bounds__(256, 2) k_attn(
    const __half* __restrict__ Qm, const __half* __restrict__ Km, const __half* __restrict__ Vm,
    const float* __restrict__ comp, const int* __restrict__ xmask, const int* __restrict__ smask)
{
    extern __shared__ unsigned char smraw[];
    __half* smh = (__half*)smraw;
    __half* Qh = smh;
    __half* Kh = smh + AT_K;
    __half* Vh = smh + AT_V;
    float*  Cs = (float*)(smraw + AT_CB);
    int*    sms = (int*)(smraw + AT_CB + 1056*4);
    int*    xm  = sms + 32;

    int tid = threadIdx.x;
    int w = tid >> 5, lane = tid & 31;
    int h = w & 3, wm = w >> 2;
    int g4 = lane >> 2, tig = lane & 3;
    int lrow = (lane & 7) + ((lane >> 3) & 1)*8;
    int lcol8 = (lane >> 4)*8;
    int l0 = blockIdx.x * 32;
    int sp = blockIdx.y, b = blockIdx.z;
    int dbase = h*64;

    unsigned sb = (unsigned)__cvta_generic_to_shared(smh);
    unsigned qb = sb;
    unsigned kb = sb + AT_K*2;
    unsigned vb = sb + AT_V*2;
    unsigned pbsu = sb + (AT_K + h*1280)*2;    // P[h] overlays K region
    __half* Ph = Kh + h*1280;

    // stage Q (32x256 halves, direct uint4 copy)
    #pragma unroll
    for (int i = 0; i < 4; i++){
        int id = tid + i*256;
        int r = id >> 5, c8 = (id & 31) << 3;
        *(uint4*)&Qh[r*QH + c8] = *(const uint4*)(Qm + (b*LQ + l0 + r)*256 + c8);
    }
    if (tid < 32) xm[tid] = xmask[b*LQ + l0 + tid];

    float o[8][4];
    #pragma unroll
    for (int nt = 0; nt < 8; nt++)
        #pragma unroll
        for (int i = 0; i < 4; i++) o[nt][i] = 0.f;
    float rmax[2] = {-1e30f, -1e30f};
    float rsum[2] = {0.f, 0.f};

    int rl = wm*16 + g4;
    for (int t = 0; t < (LQ/SPLITS)/32; t++){
        int s0 = sp*(LQ/SPLITS) + t*32;
        __syncthreads();     // prev tile fully consumed
        // K, V tiles 32x256 halves, direct uint4 copies
        #pragma unroll
        for (int i = 0; i < 4; i++){
            int id = tid + i*256;
            int r = id >> 5, c8 = (id & 31) << 3;
            long grow = (long)(b*LQ + s0 + r)*256 + c8;
            *(uint4*)&Kh[r*QH + c8] = *(const uint4*)(Km + grow);
            *(uint4*)&Vh[r*QH + c8] = *(const uint4*)(Vm + grow);
        }
        // comp tile 32x32, pre-scaled by 1/8
        {
            int r = tid >> 5, c = tid & 31;
            #pragma unroll
            for (int i = 0; i < 4; i++)
                Cs[(r + i*8)*CS_STR + c] = comp[(long)(b*LQ + l0 + r + i*8)*LQ + s0 + c] * 0.125f;
        }
        if (tid < 32) sms[tid] = smask[b*LQ + s0 + tid];
        __syncthreads();     // tiles ready

        // ---- QK^T: S[16l x 32s] per warp ----
        float S[4][4];
        #pragma unroll
        for (int nt = 0; nt < 4; nt++)
            #pragma unroll
            for (int i = 0; i < 4; i++) S[nt][i] = 0.f;
        #pragma unroll
        for (int kk = 0; kk < 4; kk++){
            int k0 = dbase + kk*16;
            unsigned a[4];
            ldsm4(a, qb + ((wm*16 + lrow)*QH + k0 + lcol8)*2);
            #pragma unroll
            for (int sh = 0; sh < 2; sh++){
                unsigned bk[4];
                ldsm4(bk, kb + ((sh*16 + lrow)*QH + k0 + lcol8)*2);
                unsigned b0[2] = {bk[0], bk[2]};
                unsigned b1[2] = {bk[1], bk[3]};
                mma16(S[sh*2],   a, b0);
                mma16(S[sh*2+1], a, b1);
            }
        }
        __syncthreads();     // all K reads done before P overlays K

        // ---- softmax (warp-local rows) ----
        int xml = xm[rl], xmh = xm[rl + 8];
        float tmaxl = -1e30f, tmaxh = -1e30f;
        #pragma unroll
        for (int nt = 0; nt < 4; nt++){
            int se = nt*8 + 2*tig, so = se + 1;
            int mse = sms[se], mso = sms[so];
            float ce = Cs[rl*CS_STR + se],      co = Cs[rl*CS_STR + so];
            float de = Cs[(rl+8)*CS_STR + se],  dox = Cs[(rl+8)*CS_STR + so];
            float v0 = (xml && !mse) ? -1e30f : S[nt][0]*ce;
            float v1 = (xml && !mso) ? -1e30f : S[nt][1]*co;
            float v2 = (xmh && !mse) ? -1e30f : S[nt][2]*de;
            float v3 = (xmh && !mso) ? -1e30f : S[nt][3]*dox;
            S[nt][0]=v0; S[nt][1]=v1; S[nt][2]=v2; S[nt][3]=v3;
            tmaxl = fmaxf(tmaxl, fmaxf(v0, v1));
            tmaxh = fmaxf(tmaxh, fmaxf(v2, v3));
        }
        tmaxl = fmaxf(tmaxl, __shfl_xor_sync(~0u, tmaxl, 1));
        tmaxl = fmaxf(tmaxl, __shfl_xor_sync(~0u, tmaxl, 2));
        tmaxh = fmaxf(tmaxh, __shfl_xor_sync(~0u, tmaxh, 1));
        tmaxh = fmaxf(tmaxh, __shfl_xor_sync(~0u, tmaxh, 2));
        float ml = fmaxf(rmax[0], tmaxl), mh = fmaxf(rmax[1], tmaxh);
        float al = fast_exp(rmax[0] - ml), ah = fast_exp(rmax[1] - mh);
        rmax[0] = ml; rmax[1] = mh;
        float tsl = 0.f, tsh = 0.f;
        #pragma unroll
        for (int nt = 0; nt < 4; nt++){
            float p0 = fast_exp(S[nt][0] - ml);
            float p1 = fast_exp(S[nt][1] - ml);
            float p2 = fast_exp(S[nt][2] - mh);
            float p3 = fast_exp(S[nt][3] - mh);
            tsl += p0 + p1; tsh += p2 + p3;
            int se = nt*8 + 2*tig;
            *(unsigned*)&Ph[rl*PH + se]     = h2pk(p0, p1);
            *(unsigned*)&Ph[(rl+8)*PH + se] = h2pk(p2, p3);
        }
        tsl += __shfl_xor_sync(~0u, tsl, 1); tsl += __shfl_xor_sync(~0u, tsl, 2);
        tsh += __shfl_xor_sync(~0u, tsh, 1); tsh += __shfl_xor_sync(~0u, tsh, 2);
        rsum[0] = rsum[0]*al + tsl;
        rsum[1] = rsum[1]*ah + tsh;
        #pragma unroll
        for (int nt = 0; nt < 8; nt++){
            o[nt][0] *= al; o[nt][1] *= al;
            o[nt][2] *= ah; o[nt][3] *= ah;
        }
        __syncwarp();        // P producer == consumer (same warp)

        // ---- P @ V: o[16l x 64d] ----
        #pragma unroll
        for (int kk = 0; kk < 2; kk++){
            unsigned a[4];
            ldsm4(a, pbsu + ((wm*16 + lrow)*PH + kk*16 + lcol8)*2);
            #pragma unroll
            for (int j = 0; j < 4; j++){
                unsigned bv[4];
                ldsm4t(bv, vb + ((kk*16 + lrow)*QH + dbase + j*16 + lcol8)*2);
                unsigned b0[2] = {bv[0], bv[1]};
                unsigned b1[2] = {bv[2], bv[3]};
                mma16(o[2*j],   a, b0);
                mma16(o[2*j+1], a, b1);
            }
        }
    }

    // ---- write unnormalized partials + stats ----
    long prow = (long)(sp*MROWS + b*LQ + l0 + rl);
    #pragma unroll
    for (int nt = 0; nt < 8; nt++){
        int col = dbase + nt*8 + 2*tig;
        *(float2*)(g_part + prow*256 + col)     = make_float2(o[nt][0], o[nt][1]);
        *(float2*)(g_part + (prow+8)*256 + col) = make_float2(o[nt][2], o[nt][3]);
    }
    if (tig == 0){
        long base = (prow*4 + h)*2;
        g_pstat[base]   = rmax[0];
        g_pstat[base+1] = rsum[0];
        long baseh = ((prow+8)*4 + h)*2;
        g_pstat[baseh]   = rmax[1];
        g_pstat[baseh+1] = rsum[1];
    }
}

// merge the KV-split partials -> g_O
__global__ void __launch_bounds__(256) k_attnmerge(int dummy)
{
    int r = blockIdx.x;
    int c = threadIdx.x;
    int h = c >> 6;
    float m0 = g_pstat[(((long)0*MROWS + r)*4 + h)*2];
    float s0 = g_pstat[(((long)0*MROWS + r)*4 + h)*2 + 1];
    float m1 = g_pstat[(((long)1*MROWS + r)*4 + h)*2];
    float s1 = g_pstat[(((long)1*MROWS + r)*4 + h)*2 + 1];
    float M = fmaxf(m0, m1);
    float w0 = fast_exp(m0 - M), w1 = fast_exp(m1 - M);
    float inv = 1.0f / (s0*w0 + s1*w1);
    float p0 = g_part[((long)0*MROWS + r)*256 + c];
    float p1 = g_part[((long)1*MROWS + r)*256 + c];
    g_O[(long)r*256 + c] = (p0*w0 + p1*w1) * inv;
}

// ---------------------------------------------------------------------------
extern "C" void kernel_launch(void* const* d_in, const int* in_sizes, int n_in,
                              void* d_out, int out_size)
{
    const float* x    = (const float*)d_in[0];
    const float* src  = (const float*)d_in[1];
    const float* xpe  = (const float*)d_in[2];
    const float* spe  = (const float*)d_in[3];
    const int* xmask  = (const int*)d_in[4];
    const int* smask  = (const int*)d_in[5];
    const float* comp = (const float*)d_in[6];
    const float* Wq   = (const float*)d_in[7];
    const float* Wk   = (const float*)d_in[8];
    const float* Wv   = (const float*)d_in[9];
    const float* Wmg  = (const float*)d_in[10];
    const float* Wm1  = (const float*)d_in[11];
    const float* Wm2  = (const float*)d_in[12];
    const float* ln1g = (const float*)d_in[13];
    const float* ln1b = (const float*)d_in[14];
    const float* ln2g = (const float*)d_in[15];
    const float* ln2b = (const float*)d_in[16];
    float* out = (float*)d_out;

    __half *Qp, *Kp, *Vp;
    cudaGetSymbolAddress((void**)&Qp, g_Qh);
    cudaGetSymbolAddress((void**)&Kp, g_Kh);
    cudaGetSymbolAddress((void**)&Vp, g_Vh);

    cudaFuncSetAttribute(k_attn, cudaFuncAttributeMaxDynamicSharedMemorySize, ATTN_BYTES);

    k_qkv <<<dim3(MROWS/32, 1, 3), 256, SM_GEMM>>>(x, xpe, src, spe, Wq, Wk, Wv);
    k_attn<<<dim3(LQ/32, SPLITS, BSZ), 256, ATTN_BYTES>>>(Qp, Kp, Vp, comp, xmask, smask);
    k_attnmerge<<<MROWS, 256>>>(0);
    k_merge<<<MROWS/32,            256, SM_GEMM>>>(Wmg, ln1g, ln1b);
    k_mlp1<<<dim3(MROWS/32, 2),    256, SM_GEMM>>>(x, Wm1);
    k_mlp2<<<MROWS/32,             256, SM_GEMM>>>(Wm2, ln2g, ln2b, x, out);
}